// round 7
// baseline (speedup 1.0000x reference)
#include <cuda_runtime.h>
#include <cuda_bf16.h>
#include <cuda_fp16.h>
#include <cuda_fp8.h>
#include <cstdint>

#define BSZ 2
#define SEQL 2048
#define EMB 1024
#define NH 16
#define HD 64
#define MROWS (BSZ * SEQL)

// ---------------- scratch (__device__ globals; no allocs allowed) ----------
// fp16-hi + fp8-hi + fp8-lo(scaled 2^12) trios for GEMM operands
__device__ __half g_x16[MROWS * EMB];
__device__ uint8_t g_x8h[MROWS * EMB], g_x8l[MROWS * EMB];
__device__ __half g_a16[MROWS * EMB];
__device__ uint8_t g_a8h[MROWS * EMB], g_a8l[MROWS * EMB];
__device__ __half g_wq16[EMB * EMB];
__device__ uint8_t g_wq8h[EMB * EMB], g_wq8l[EMB * EMB];
__device__ __half g_wk16[EMB * EMB];
__device__ uint8_t g_wk8h[EMB * EMB], g_wk8l[EMB * EMB];
__device__ __half g_wv16[EMB * EMB];
__device__ uint8_t g_wv8h[EMB * EMB], g_wv8l[EMB * EMB];
__device__ __half g_wo16[EMB * EMB];
__device__ uint8_t g_wo8h[EMB * EMB], g_wo8l[EMB * EMB];
// bf16 hi/lo Q/K/V for the (unchanged) bf16x3 attention
__device__ __nv_bfloat16 g_qhi[BSZ * NH * SEQL * HD], g_qlo[BSZ * NH * SEQL * HD];
__device__ __nv_bfloat16 g_khi[BSZ * NH * SEQL * HD], g_klo[BSZ * NH * SEQL * HD];
__device__ __nv_bfloat16 g_vhi[BSZ * NH * SEQL * HD], g_vlo[BSZ * NH * SEQL * HD];

// ---------------- PTX helpers (family-compatible, sm_80/89-era) -------------
__device__ __forceinline__ uint32_t s2u(const void* p) {
    uint32_t a;
    asm("{ .reg .u64 t; cvta.to.shared.u64 t, %1; cvt.u32.u64 %0, t; }"
        : "=r"(a) : "l"(p));
    return a;
}
__device__ __forceinline__ void cpa16(uint32_t d, const void* g) {
    asm volatile("cp.async.cg.shared.global [%0], [%1], 16;" :: "r"(d), "l"(g));
}
#define CP_COMMIT() asm volatile("cp.async.commit_group;" ::: "memory")
#define CP_WAIT(n) asm volatile("cp.async.wait_group %0;" :: "n"(n) : "memory")

__device__ __forceinline__ void ldsm4(uint32_t* r, uint32_t a) {
    asm volatile("ldmatrix.sync.aligned.m8n8.x4.shared.b16 {%0,%1,%2,%3}, [%4];"
                 : "=r"(r[0]), "=r"(r[1]), "=r"(r[2]), "=r"(r[3]) : "r"(a));
}
__device__ __forceinline__ void ldsm2(uint32_t* r, uint32_t a) {
    asm volatile("ldmatrix.sync.aligned.m8n8.x2.shared.b16 {%0,%1}, [%2];"
                 : "=r"(r[0]), "=r"(r[1]) : "r"(a));
}
__device__ __forceinline__ void ldsm2t(uint32_t* r, uint32_t a) {
    asm volatile("ldmatrix.sync.aligned.m8n8.x2.trans.shared.b16 {%0,%1}, [%2];"
                 : "=r"(r[0]), "=r"(r[1]) : "r"(a));
}
__device__ __forceinline__ uint32_t lds32(uint32_t a) {
    uint32_t v;
    asm volatile("ld.shared.b32 %0, [%1];" : "=r"(v) : "r"(a));
    return v;
}
__device__ __forceinline__ void mma_bf16(float* c, const uint32_t* a, const uint32_t* b) {
    asm volatile(
        "mma.sync.aligned.m16n8k16.row.col.f32.bf16.bf16.f32 "
        "{%0,%1,%2,%3}, {%4,%5,%6,%7}, {%8,%9}, {%0,%1,%2,%3};"
        : "+f"(c[0]), "+f"(c[1]), "+f"(c[2]), "+f"(c[3])
        : "r"(a[0]), "r"(a[1]), "r"(a[2]), "r"(a[3]), "r"(b[0]), "r"(b[1]));
}
__device__ __forceinline__ void mma_f16(float* c, const uint32_t* a, const uint32_t* b) {
    asm volatile(
        "mma.sync.aligned.m16n8k16.row.col.f32.f16.f16.f32 "
        "{%0,%1,%2,%3}, {%4,%5,%6,%7}, {%8,%9}, {%0,%1,%2,%3};"
        : "+f"(c[0]), "+f"(c[1]), "+f"(c[2]), "+f"(c[3])
        : "r"(a[0]), "r"(a[1]), "r"(a[2]), "r"(a[3]), "r"(b[0]), "r"(b[1]));
}
__device__ __forceinline__ void mma_f8(float* c, const uint32_t* a, const uint32_t* b) {
    asm volatile(
        "mma.sync.aligned.m16n8k32.row.col.f32.e4m3.e4m3.f32 "
        "{%0,%1,%2,%3}, {%4,%5,%6,%7}, {%8,%9}, {%0,%1,%2,%3};"
        : "+f"(c[0]), "+f"(c[1]), "+f"(c[2]), "+f"(c[3])
        : "r"(a[0]), "r"(a[1]), "r"(a[2]), "r"(a[3]), "r"(b[0]), "r"(b[1]));
}
// bf16 split (attention path)
__device__ __forceinline__ void split2(float x, float y, uint32_t& h, uint32_t& l) {
    __nv_bfloat16 hx = __float2bfloat16(x);
    __nv_bfloat16 hy = __float2bfloat16(y);
    __nv_bfloat162 hv(hx, hy);
    __nv_bfloat162 lv(__float2bfloat16(x - __bfloat162float(hx)),
                      __float2bfloat16(y - __bfloat162float(hy)));
    h = *(uint32_t*)&hv;
    l = *(uint32_t*)&lv;
}
// fp16+fp8 trio emit for a pair of values
__device__ __forceinline__ void store3(float v0, float v1, __half* O16,
                                       uint8_t* O8h, uint8_t* O8l, size_t idx) {
    __half2 h2 = __floats2half2_rn(v0, v1);
    *(__half2*)&O16[idx] = h2;
    __nv_fp8x2_storage_t ph =
        __nv_cvt_float2_to_fp8x2(make_float2(v0, v1), __NV_SATFINITE, __NV_E4M3);
    *(uint16_t*)&O8h[idx] = (uint16_t)ph;
    float l0 = (v0 - __low2float(h2)) * 4096.0f;
    float l1 = (v1 - __high2float(h2)) * 4096.0f;
    __nv_fp8x2_storage_t pl =
        __nv_cvt_float2_to_fp8x2(make_float2(l0, l1), __NV_SATFINITE, __NV_E4M3);
    *(uint16_t*)&O8l[idx] = (uint16_t)pl;
}

// ---------------- fp32 -> fp16-hi + fp8-hi + fp8-lo(x4096) ------------------
__global__ __launch_bounds__(256) void cvt3(const float* __restrict__ in,
                                            __half* __restrict__ h16,
                                            uint8_t* __restrict__ h8,
                                            uint8_t* __restrict__ l8, int n4) {
    int i = blockIdx.x * 256 + threadIdx.x;
    if (i >= n4) return;
    float4 v = ((const float4*)in)[i];
    __half2 ha = __floats2half2_rn(v.x, v.y);
    __half2 hb = __floats2half2_rn(v.z, v.w);
    ((__half2*)h16)[2 * i] = ha;
    ((__half2*)h16)[2 * i + 1] = hb;
    uint32_t pa = __nv_cvt_float2_to_fp8x2(make_float2(v.x, v.y), __NV_SATFINITE, __NV_E4M3);
    uint32_t pb = __nv_cvt_float2_to_fp8x2(make_float2(v.z, v.w), __NV_SATFINITE, __NV_E4M3);
    ((uint32_t*)h8)[i] = pa | (pb << 16);
    float2 la = make_float2((v.x - __low2float(ha)) * 4096.0f,
                            (v.y - __high2float(ha)) * 4096.0f);
    float2 lb = make_float2((v.z - __low2float(hb)) * 4096.0f,
                            (v.w - __high2float(hb)) * 4096.0f);
    uint32_t qa = __nv_cvt_float2_to_fp8x2(la, __NV_SATFINITE, __NV_E4M3);
    uint32_t qb = __nv_cvt_float2_to_fp8x2(lb, __NV_SATFINITE, __NV_E4M3);
    ((uint32_t*)l8)[i] = qa | (qb << 16);
}

// ---------------- fp16-hi + fp8-cross GEMM: C = A @ B^T ---------------------
// CTA tile 128x128, BK=32, 3-stage cp.async. 8 warps: 4(m) x 2(n).
// Per chunk: 32 fp16 m16n8k16 MMAs (hi.hi) + 32 e4m3 m16n8k32 MMAs (cross).
// MODE 0: fp32 C row-major; MODE 1: bf16 hi/lo scatter to [b,h,s,d]
#define TM 128
#define TN 128
#define KB 32
#define NCH (EMB / KB)
#define P16 80                       // fp16 tile row pitch (64B data + 16B pad)
#define A16SZ (128 * P16)            // 10240
#define A8SZ (128 * 32)              // 4096 (fp8, swizzled, no pad)
#define OA16 0
#define OB16 A16SZ
#define OA8H (2 * A16SZ)
#define OA8L (2 * A16SZ + A8SZ)
#define OB8H (2 * A16SZ + 2 * A8SZ)
#define OB8L (2 * A16SZ + 3 * A8SZ)
#define STAGE_B (2 * A16SZ + 4 * A8SZ)   // 36864
#define SM_TOTAL (3 * STAGE_B)           // 110592

// 16B-chunk XOR swizzle for fp8 tiles: row r (32B = 2 chunks), chunk j, word c
__device__ __forceinline__ uint32_t f8addr(uint32_t base, int r, int j, int c) {
    int s = (r & 1) ^ ((r >> 2) & 1);
    return base + r * 32 + ((j ^ s) << 4) + (c << 2);
}

template <int MODE>
__global__ __launch_bounds__(256, 1)
void gemm_mma(const __half* __restrict__ A16, const uint8_t* __restrict__ A8h,
              const uint8_t* __restrict__ A8l,
              const __half* __restrict__ B16, const uint8_t* __restrict__ B8h,
              const uint8_t* __restrict__ B8l,
              float* __restrict__ C,
              __nv_bfloat16* __restrict__ Chi, __nv_bfloat16* __restrict__ Clo) {
    extern __shared__ __align__(128) char smem[];
    const uint32_t sb = s2u(smem);
    const int tid = threadIdx.x;
    const int wid = tid >> 5;
    const int lane = tid & 31;
    const int m0 = blockIdx.y * TM;
    const int n0 = blockIdx.x * TN;
    const int wm0 = (wid >> 1) * 32;
    const int wn0 = (wid & 1) * 64;

    // gmem load geometry
    const int r16 = tid >> 2;          // fp16: row, 4 chunks/row
    const int c16 = tid & 3;
    const __half* pA16 = A16 + (size_t)(m0 + r16) * EMB + c16 * 8;
    const __half* pB16 = B16 + (size_t)(n0 + r16) * EMB + c16 * 8;
    const int r8 = tid >> 1;           // fp8: row, 2 chunks/row
    const int j8 = tid & 1;
    const uint8_t* pA8h = A8h + (size_t)(m0 + r8) * EMB + j8 * 16;
    const uint8_t* pA8l = A8l + (size_t)(m0 + r8) * EMB + j8 * 16;
    const uint8_t* pB8h = B8h + (size_t)(n0 + r8) * EMB + j8 * 16;
    const uint8_t* pB8l = B8l + (size_t)(n0 + r8) * EMB + j8 * 16;

    auto load_chunk = [&](int c, int s) {
        const uint32_t base = sb + s * STAGE_B;
        const int kb = c * KB;
#pragma unroll
        for (int i = 0; i < 2; i++) {
            const uint32_t so = (r16 + 64 * i) * P16 + c16 * 16;
            const size_t go = (size_t)(64 * i) * EMB + kb;
            cpa16(base + OA16 + so, pA16 + go);
            cpa16(base + OB16 + so, pB16 + go);
        }
        cpa16(f8addr(base + OA8H, r8, j8, 0), pA8h + kb);
        cpa16(f8addr(base + OA8L, r8, j8, 0), pA8l + kb);
        cpa16(f8addr(base + OB8H, r8, j8, 0), pB8h + kb);
        cpa16(f8addr(base + OB8L, r8, j8, 0), pB8l + kb);
        CP_COMMIT();
    };

    float acc[2][8][4];   // fp16 hi.hi accumulator
    float acc2[2][8][4];  // fp8 cross accumulator (scaled x4096)
#pragma unroll
    for (int mf = 0; mf < 2; mf++)
#pragma unroll
        for (int nf = 0; nf < 8; nf++)
#pragma unroll
            for (int j = 0; j < 4; j++) { acc[mf][nf][j] = 0.0f; acc2[mf][nf][j] = 0.0f; }

    const uint32_t aRow = wm0 + (lane & 15);
    const uint32_t aHalf = (lane >> 4) * 16;
    const uint32_t bRow = wn0 + (lane & 7);
    const uint32_t bHalf = ((lane >> 3) & 1) * 16;
    const int fr = lane >> 2;   // fp8 fragment row within group
    const int fc = lane & 3;    // fp8 fragment 4B word

    load_chunk(0, 0);
    load_chunk(1, 1);

    for (int c = 0; c < NCH; c++) {
        const int s = c - (c / 3) * 3;
        if (c + 2 < NCH) { CP_WAIT(1); } else { CP_WAIT(0); }
        __syncthreads();
        if (c + 2 < NCH) load_chunk(c + 2, s == 0 ? 2 : s - 1);

        const uint32_t st = sb + s * STAGE_B;
        // fp16 hi.hi path
#pragma unroll
        for (int kk = 0; kk < 2; kk++) {
            uint32_t ah[2][4];
#pragma unroll
            for (int mf = 0; mf < 2; mf++)
                ldsm4(ah[mf], st + OA16 + (aRow + mf * 16) * P16 + kk * 32 + aHalf);
#pragma unroll
            for (int nf = 0; nf < 8; nf++) {
                uint32_t bh[2];
                ldsm2(bh, st + OB16 + (bRow + nf * 8) * P16 + kk * 32 + bHalf);
#pragma unroll
                for (int mf = 0; mf < 2; mf++) mma_f16(acc[mf][nf], ah[mf], bh);
            }
        }
        // fp8 cross path: one k32 MMA pair covers the whole chunk
        uint32_t a8h[2][4], a8l[2][4];
#pragma unroll
        for (int mf = 0; mf < 2; mf++) {
            const int ar = wm0 + mf * 16 + fr;
            a8h[mf][0] = lds32(f8addr(st + OA8H, ar, 0, fc));
            a8h[mf][1] = lds32(f8addr(st + OA8H, ar + 8, 0, fc));
            a8h[mf][2] = lds32(f8addr(st + OA8H, ar, 1, fc));
            a8h[mf][3] = lds32(f8addr(st + OA8H, ar + 8, 1, fc));
            a8l[mf][0] = lds32(f8addr(st + OA8L, ar, 0, fc));
            a8l[mf][1] = lds32(f8addr(st + OA8L, ar + 8, 0, fc));
            a8l[mf][2] = lds32(f8addr(st + OA8L, ar, 1, fc));
            a8l[mf][3] = lds32(f8addr(st + OA8L, ar + 8, 1, fc));
        }
#pragma unroll
        for (int nf = 0; nf < 8; nf++) {
            const int bn = wn0 + nf * 8 + fr;
            uint32_t b8h[2], b8l[2];
            b8h[0] = lds32(f8addr(st + OB8H, bn, 0, fc));
            b8h[1] = lds32(f8addr(st + OB8H, bn, 1, fc));
            b8l[0] = lds32(f8addr(st + OB8L, bn, 0, fc));
            b8l[1] = lds32(f8addr(st + OB8L, bn, 1, fc));
#pragma unroll
            for (int mf = 0; mf < 2; mf++) {
                mma_f8(acc2[mf][nf], a8h[mf], b8l);   // A  * Blo*4096
                mma_f8(acc2[mf][nf], a8l[mf], b8h);   // Alo*4096 * B
            }
        }
    }

    // epilogue: C = acc + acc2/4096
#pragma unroll
    for (int mf = 0; mf < 2; mf++) {
        const int mrow = m0 + wm0 + mf * 16 + (lane >> 2);
#pragma unroll
        for (int half = 0; half < 2; half++) {
            const int row = mrow + half * 8;
            const int b = row >> 11;
            const int sdx = row & (SEQL - 1);
#pragma unroll
            for (int nf = 0; nf < 8; nf++) {
                const int col = n0 + wn0 + nf * 8 + 2 * (lane & 3);
                const float c0 =
                    acc[mf][nf][2 * half] + acc2[mf][nf][2 * half] * (1.0f / 4096.0f);
                const float c1 =
                    acc[mf][nf][2 * half + 1] + acc2[mf][nf][2 * half + 1] * (1.0f / 4096.0f);
                if (MODE == 0) {
                    float2 v = {c0, c1};
                    *(float2*)&C[(size_t)row * EMB + col] = v;
                } else {
                    const int h = col >> 6;
                    const int d = col & 63;
                    uint32_t hv, lv;
                    split2(c0, c1, hv, lv);
                    const size_t idx = (((size_t)(b * NH + h) * SEQL + sdx) << 6) + d;
                    *(uint32_t*)&Chi[idx] = hv;
                    *(uint32_t*)&Clo[idx] = lv;
                }
            }
        }
    }
}

// ---------------- tensor-core causal flash attention (bf16x3) ----------------
#define QT 128
#define ST 64
#define KROWB 144
#define KVTILE (ST * KROWB)
#define AT_STAGE (4 * KVTILE)
#define AT_SMEM (2 * AT_STAGE)

__global__ __launch_bounds__(256, 1)
void attn_mma(const __nv_bfloat16* __restrict__ Qhi, const __nv_bfloat16* __restrict__ Qlo,
              const __nv_bfloat16* __restrict__ Khi, const __nv_bfloat16* __restrict__ Klo,
              const __nv_bfloat16* __restrict__ Vhi, const __nv_bfloat16* __restrict__ Vlo,
              __half* __restrict__ O16, uint8_t* __restrict__ O8h,
              uint8_t* __restrict__ O8l) {
    extern __shared__ __align__(128) char smem[];
    const uint32_t sb = s2u(smem);
    const int tid = threadIdx.x;
    const int wid = tid >> 5;
    const int lane = tid & 31;
    const int qt = (SEQL / QT - 1) - (blockIdx.x >> 5);  // heavy tiles first
    const int bh = blockIdx.x & 31;
    const size_t hoff = (size_t)bh * SEQL * HD;

#define QSTG (QT * KROWB)
    {
        const int r = tid >> 1;
        const int cs = (tid & 1) * 4;
        const __nv_bfloat16* qh = Qhi + hoff + (size_t)(qt * QT + r) * HD + cs * 8;
        const __nv_bfloat16* ql = Qlo + hoff + (size_t)(qt * QT + r) * HD + cs * 8;
#pragma unroll
        for (int i = 0; i < 4; i++) {
            cpa16(sb + r * KROWB + (cs + i) * 16, qh + i * 8);
            cpa16(sb + QSTG + r * KROWB + (cs + i) * 16, ql + i * 8);
        }
        CP_COMMIT();
        CP_WAIT(0);
        __syncthreads();
    }
    uint32_t qah[4][4], qal[4][4];
    {
        const uint32_t qa0 = (16 * wid + (lane & 15)) * KROWB + (lane >> 4) * 16;
#pragma unroll
        for (int kk = 0; kk < 4; kk++) {
            ldsm4(qah[kk], sb + qa0 + kk * 32);
            ldsm4(qal[kk], sb + QSTG + qa0 + kk * 32);
        }
    }
    __syncthreads();

    auto load_kv = [&](int c, int stg) {
        const uint32_t base = sb + stg * AT_STAGE;
        const size_t g0 = hoff + (size_t)(c * ST) * HD;
#pragma unroll
        for (int i = 0; i < 2; i++) {
            const int id = tid + 256 * i;
            const int r = id >> 3;
            const int sg = id & 7;
            const uint32_t so = r * KROWB + sg * 16;
            const size_t go = g0 + (size_t)r * HD + sg * 8;
            cpa16(base + so, Khi + go);
            cpa16(base + KVTILE + so, Klo + go);
            cpa16(base + 2 * KVTILE + so, Vhi + go);
            cpa16(base + 3 * KVTILE + so, Vlo + go);
        }
        CP_COMMIT();
    };

    float m_[2] = {-1e30f, -1e30f};
    float l_[2] = {0.0f, 0.0f};
    float o[8][4];
#pragma unroll
    for (int nf = 0; nf < 8; nf++)
#pragma unroll
        for (int j = 0; j < 4; j++) o[nf][j] = 0.0f;

    const int nch = 2 * qt + 2;
    load_kv(0, 0);
    if (nch > 1) load_kv(1, 1);

    const int rowa = qt * QT + 16 * wid + (lane >> 2);

    for (int c = 0; c < nch; c++) {
        if (c + 1 < nch) { CP_WAIT(1); } else { CP_WAIT(0); }
        __syncthreads();
        const uint32_t st = sb + (c & 1) * AT_STAGE;

        float s[8][4];
#pragma unroll
        for (int nf = 0; nf < 8; nf++)
#pragma unroll
            for (int j = 0; j < 4; j++) s[nf][j] = 0.0f;
#pragma unroll
        for (int kk = 0; kk < 4; kk++) {
#pragma unroll
            for (int nf = 0; nf < 8; nf++) {
                uint32_t kh[2], kl[2];
                const uint32_t bo =
                    (nf * 8 + (lane & 7)) * KROWB + kk * 32 + ((lane >> 3) & 1) * 16;
                ldsm2(kh, st + bo);
                ldsm2(kl, st + KVTILE + bo);
                mma_bf16(s[nf], qah[kk], kh);
                mma_bf16(s[nf], qah[kk], kl);
                mma_bf16(s[nf], qal[kk], kh);
            }
        }

        const bool diagc = (c >= 2 * qt);
#pragma unroll
        for (int nf = 0; nf < 8; nf++) {
#pragma unroll
            for (int j = 0; j < 4; j++) {
                float v = s[nf][j] * 0.125f;
                if (diagc) {
                    const int col = c * ST + nf * 8 + 2 * (lane & 3) + (j & 1);
                    const int row = rowa + ((j >> 1) << 3);
                    if (col > row) v = -1e30f;
                }
                s[nf][j] = v;
            }
        }

        float rma = -1e30f, rmb = -1e30f;
#pragma unroll
        for (int nf = 0; nf < 8; nf++) {
            rma = fmaxf(rma, fmaxf(s[nf][0], s[nf][1]));
            rmb = fmaxf(rmb, fmaxf(s[nf][2], s[nf][3]));
        }
        rma = fmaxf(rma, __shfl_xor_sync(0xffffffffu, rma, 1));
        rma = fmaxf(rma, __shfl_xor_sync(0xffffffffu, rma, 2));
        rmb = fmaxf(rmb, __shfl_xor_sync(0xffffffffu, rmb, 1));
        rmb = fmaxf(rmb, __shfl_xor_sync(0xffffffffu, rmb, 2));

        const float mna = fmaxf(m_[0], rma);
        const float mnb = fmaxf(m_[1], rmb);
        const float ca = __expf(m_[0] - mna);
        const float cb = __expf(m_[1] - mnb);
        float sa = 0.0f, sbv = 0.0f;
#pragma unroll
        for (int nf = 0; nf < 8; nf++) {
            s[nf][0] = __expf(s[nf][0] - mna);
            s[nf][1] = __expf(s[nf][1] - mna);
            s[nf][2] = __expf(s[nf][2] - mnb);
            s[nf][3] = __expf(s[nf][3] - mnb);
            sa += s[nf][0] + s[nf][1];
            sbv += s[nf][2] + s[nf][3];
        }
        sa += __shfl_xor_sync(0xffffffffu, sa, 1);
        sa += __shfl_xor_sync(0xffffffffu, sa, 2);
        sbv += __shfl_xor_sync(0xffffffffu, sbv, 1);
        sbv += __shfl_xor_sync(0xffffffffu, sbv, 2);
        l_[0] = l_[0] * ca + sa;
        l_[1] = l_[1] * cb + sbv;
        m_[0] = mna;
        m_[1] = mnb;
#pragma unroll
        for (int nf = 0; nf < 8; nf++) {
            o[nf][0] *= ca;
            o[nf][1] *= ca;
            o[nf][2] *= cb;
            o[nf][3] *= cb;
        }

#pragma unroll
        for (int kk = 0; kk < 4; kk++) {
            uint32_t pah[4], pal[4];
            split2(s[2 * kk][0], s[2 * kk][1], pah[0], pal[0]);
            split2(s[2 * kk][2], s[2 * kk][3], pah[1], pal[1]);
            split2(s[2 * kk + 1][0], s[2 * kk + 1][1], pah[2], pal[2]);
            split2(s[2 * kk + 1][2], s[2 * kk + 1][3], pah[3], pal[3]);
#pragma unroll
            for (int nf = 0; nf < 8; nf++) {
                uint32_t vh[2], vl[2];
                const uint32_t vo = (kk * 16 + (lane & 15)) * KROWB + nf * 16;
                ldsm2t(vh, st + 2 * KVTILE + vo);
                ldsm2t(vl, st + 3 * KVTILE + vo);
                mma_bf16(o[nf], pah, vh);
                mma_bf16(o[nf], pah, vl);
                mma_bf16(o[nf], pal, vh);
            }
        }
        __syncthreads();
        if (c + 2 < nch) load_kv(c + 2, c & 1);
    }

    // epilogue: normalize -> fp16/fp8 trio for the output projection GEMM
    const int b = bh >> 4;
    const int h = bh & 15;
    const float ia = 1.0f / l_[0];
    const float ib = 1.0f / l_[1];
#pragma unroll
    for (int nf = 0; nf < 8; nf++) {
        const int e = h * 64 + nf * 8 + 2 * (lane & 3);
        size_t idx = (size_t)(b * SEQL + rowa) * EMB + e;
        store3(o[nf][0] * ia, o[nf][1] * ia, O16, O8h, O8l, idx);
        idx = (size_t)(b * SEQL + rowa + 8) * EMB + e;
        store3(o[nf][2] * ib, o[nf][3] * ib, O16, O8h, O8l, idx);
    }
}

// ---------------- launch -----------------------------------------------------
extern "C" void kernel_launch(void* const* d_in, const int* in_sizes, int n_in,
                              void* d_out, int out_size) {
    const float* x = (const float*)d_in[0];
    const float* w_q = (const float*)d_in[1];
    const float* w_k = (const float*)d_in[2];
    const float* w_v = (const float*)d_in[3];
    const float* w_o = (const float*)d_in[4];
    float* out = (float*)d_out;

    __half *x16, *a16, *wq16, *wk16, *wv16, *wo16;
    uint8_t *x8h, *x8l, *a8h, *a8l;
    uint8_t *wq8h, *wq8l, *wk8h, *wk8l, *wv8h, *wv8l, *wo8h, *wo8l;
    __nv_bfloat16 *qhi, *qlo, *khi, *klo, *vhi, *vlo;
    cudaGetSymbolAddress((void**)&x16, g_x16);
    cudaGetSymbolAddress((void**)&x8h, g_x8h);
    cudaGetSymbolAddress((void**)&x8l, g_x8l);
    cudaGetSymbolAddress((void**)&a16, g_a16);
    cudaGetSymbolAddress((void**)&a8h, g_a8h);
    cudaGetSymbolAddress((void**)&a8l, g_a8l);
    cudaGetSymbolAddress((void**)&wq16, g_wq16);
    cudaGetSymbolAddress((void**)&wq8h, g_wq8h);
    cudaGetSymbolAddress((void**)&wq8l, g_wq8l);
    cudaGetSymbolAddress((void**)&wk16, g_wk16);
    cudaGetSymbolAddress((void**)&wk8h, g_wk8h);
    cudaGetSymbolAddress((void**)&wk8l, g_wk8l);
    cudaGetSymbolAddress((void**)&wv16, g_wv16);
    cudaGetSymbolAddress((void**)&wv8h, g_wv8h);
    cudaGetSymbolAddress((void**)&wv8l, g_wv8l);
    cudaGetSymbolAddress((void**)&wo16, g_wo16);
    cudaGetSymbolAddress((void**)&wo8h, g_wo8h);
    cudaGetSymbolAddress((void**)&wo8l, g_wo8l);
    cudaGetSymbolAddress((void**)&qhi, g_qhi);
    cudaGetSymbolAddress((void**)&qlo, g_qlo);
    cudaGetSymbolAddress((void**)&khi, g_khi);
    cudaGetSymbolAddress((void**)&klo, g_klo);
    cudaGetSymbolAddress((void**)&vhi, g_vhi);
    cudaGetSymbolAddress((void**)&vlo, g_vlo);

    cudaFuncSetAttribute(gemm_mma<0>, cudaFuncAttributeMaxDynamicSharedMemorySize, SM_TOTAL);
    cudaFuncSetAttribute(gemm_mma<1>, cudaFuncAttributeMaxDynamicSharedMemorySize, SM_TOTAL);
    cudaFuncSetAttribute(attn_mma, cudaFuncAttributeMaxDynamicSharedMemorySize, AT_SMEM);

    const int nx4 = MROWS * EMB / 4;
    const int nw4 = EMB * EMB / 4;
    cvt3<<<nx4 / 256, 256>>>(x, x16, x8h, x8l, nx4);
    cvt3<<<nw4 / 256, 256>>>(w_q, wq16, wq8h, wq8l, nw4);
    cvt3<<<nw4 / 256, 256>>>(w_k, wk16, wk8h, wk8l, nw4);
    cvt3<<<nw4 / 256, 256>>>(w_v, wv16, wv8h, wv8l, nw4);
    cvt3<<<nw4 / 256, 256>>>(w_o, wo16, wo8h, wo8l, nw4);

    dim3 ggrid(EMB / TN, MROWS / TM);  // (8, 32)
    gemm_mma<1><<<ggrid, 256, SM_TOTAL>>>(x16, x8h, x8l, wq16, wq8h, wq8l,
                                          nullptr, qhi, qlo);
    gemm_mma<1><<<ggrid, 256, SM_TOTAL>>>(x16, x8h, x8l, wk16, wk8h, wk8l,
                                          nullptr, khi, klo);
    gemm_mma<1><<<ggrid, 256, SM_TOTAL>>>(x16, x8h, x8l, wv16, wv8h, wv8l,
                                          nullptr, vhi, vlo);

    attn_mma<<<(SEQL / QT) * BSZ * NH, 256, AT_SMEM>>>(qhi, qlo, khi, klo, vhi, vlo,
                                                       a16, a8h, a8l);

    gemm_mma<0><<<ggrid, 256, SM_TOTAL>>>(a16, a8h, a8l, wo16, wo8h, wo8l,
                                          out, nullptr, nullptr);
}

// round 8
// speedup vs baseline: 1.9278x; 1.9278x over previous
#include <cuda_runtime.h>
#include <cuda_bf16.h>
#include <cuda_fp16.h>
#include <cstdint>

#define BSZ 2
#define SEQL 2048
#define EMB 1024
#define NH 16
#define HD 64
#define MROWS (BSZ * SEQL)

// ---------------- scratch (__device__ globals; no allocs allowed) ----------
__device__ __nv_bfloat16 g_xhi[MROWS * EMB], g_xlo[MROWS * EMB];
__device__ __nv_bfloat16 g_ahi[MROWS * EMB], g_alo[MROWS * EMB];
__device__ __half g_q16h[BSZ * NH * SEQL * HD], g_q16l[BSZ * NH * SEQL * HD];
__device__ __half g_k16h[BSZ * NH * SEQL * HD];
__device__ __half g_v16h[BSZ * NH * SEQL * HD];
__device__ __nv_bfloat16 g_wqhi[EMB * EMB], g_wqlo[EMB * EMB];
__device__ __nv_bfloat16 g_wkhi[EMB * EMB], g_wklo[EMB * EMB];
__device__ __nv_bfloat16 g_wvhi[EMB * EMB], g_wvlo[EMB * EMB];
__device__ __nv_bfloat16 g_wohi[EMB * EMB], g_wolo[EMB * EMB];

// ---------------- PTX helpers (family-compatible, sm_80-era) ----------------
__device__ __forceinline__ uint32_t s2u(const void* p) {
    uint32_t a;
    asm("{ .reg .u64 t; cvta.to.shared.u64 t, %1; cvt.u32.u64 %0, t; }"
        : "=r"(a) : "l"(p));
    return a;
}
__device__ __forceinline__ void cpa16(uint32_t d, const void* g) {
    asm volatile("cp.async.cg.shared.global [%0], [%1], 16;" :: "r"(d), "l"(g));
}
#define CP_COMMIT() asm volatile("cp.async.commit_group;" ::: "memory")
#define CP_WAIT(n) asm volatile("cp.async.wait_group %0;" :: "n"(n) : "memory")

__device__ __forceinline__ void ldsm4(uint32_t* r, uint32_t a) {
    asm volatile("ldmatrix.sync.aligned.m8n8.x4.shared.b16 {%0,%1,%2,%3}, [%4];"
                 : "=r"(r[0]), "=r"(r[1]), "=r"(r[2]), "=r"(r[3]) : "r"(a));
}
__device__ __forceinline__ void ldsm2(uint32_t* r, uint32_t a) {
    asm volatile("ldmatrix.sync.aligned.m8n8.x2.shared.b16 {%0,%1}, [%2];"
                 : "=r"(r[0]), "=r"(r[1]) : "r"(a));
}
__device__ __forceinline__ void ldsm2t(uint32_t* r, uint32_t a) {
    asm volatile("ldmatrix.sync.aligned.m8n8.x2.trans.shared.b16 {%0,%1}, [%2];"
                 : "=r"(r[0]), "=r"(r[1]) : "r"(a));
}
__device__ __forceinline__ void mma_bf16(float* c, const uint32_t* a, const uint32_t* b) {
    asm volatile(
        "mma.sync.aligned.m16n8k16.row.col.f32.bf16.bf16.f32 "
        "{%0,%1,%2,%3}, {%4,%5,%6,%7}, {%8,%9}, {%0,%1,%2,%3};"
        : "+f"(c[0]), "+f"(c[1]), "+f"(c[2]), "+f"(c[3])
        : "r"(a[0]), "r"(a[1]), "r"(a[2]), "r"(a[3]), "r"(b[0]), "r"(b[1]));
}
__device__ __forceinline__ void mma_f16(float* c, const uint32_t* a, const uint32_t* b) {
    asm volatile(
        "mma.sync.aligned.m16n8k16.row.col.f32.f16.f16.f32 "
        "{%0,%1,%2,%3}, {%4,%5,%6,%7}, {%8,%9}, {%0,%1,%2,%3};"
        : "+f"(c[0]), "+f"(c[1]), "+f"(c[2]), "+f"(c[3])
        : "r"(a[0]), "r"(a[1]), "r"(a[2]), "r"(a[3]), "r"(b[0]), "r"(b[1]));
}
// bf16 2-way split of a float pair
__device__ __forceinline__ void split2(float x, float y, uint32_t& h, uint32_t& l) {
    __nv_bfloat16 hx = __float2bfloat16(x);
    __nv_bfloat16 hy = __float2bfloat16(y);
    __nv_bfloat162 hv(hx, hy);
    __nv_bfloat162 lv(__float2bfloat16(x - __bfloat162float(hx)),
                      __float2bfloat16(y - __bfloat162float(hy)));
    h = *(uint32_t*)&hv;
    l = *(uint32_t*)&lv;
}
// fp16 2-way split of a float pair
__device__ __forceinline__ void split2h(float x, float y, uint32_t& h, uint32_t& l) {
    __half2 hv = __floats2half2_rn(x, y);
    __half2 lv = __floats2half2_rn(x - __low2float(hv), y - __high2float(hv));
    h = *(uint32_t*)&hv;
    l = *(uint32_t*)&lv;
}

// ---------------- fp32 -> bf16 hi/lo split ----------------------------------
__global__ __launch_bounds__(256) void cvt_split(const float* __restrict__ in,
                                                 __nv_bfloat16* __restrict__ hi,
                                                 __nv_bfloat16* __restrict__ lo,
                                                 int n4) {
    int i = blockIdx.x * 256 + threadIdx.x;
    if (i >= n4) return;
    float4 v = ((const float4*)in)[i];
    uint32_t h0, l0, h1, l1;
    split2(v.x, v.y, h0, l0);
    split2(v.z, v.w, h1, l1);
    ((uint32_t*)hi)[2 * i] = h0;
    ((uint32_t*)hi)[2 * i + 1] = h1;
    ((uint32_t*)lo)[2 * i] = l0;
    ((uint32_t*)lo)[2 * i + 1] = l1;
}

// ---------------- mma.sync bf16x3 GEMM: C = A @ B^T -------------------------
// CTA tile 128x128, BK=32, 3-stage cp.async. 8 warps: 4(m) x 2(n).
// MODE 0: fp32 C row-major
// MODE 1: fp16 hi+lo scatter to [b,h,s,d]   (Q)
// MODE 2: fp16 hi only scatter to [b,h,s,d] (K, V)
#define TM 128
#define TN 128
#define KB 32
#define NCH (EMB / KB)
#define ROWB 80
#define MAT_B (128 * ROWB)
#define OFF_AH 0
#define OFF_AL MAT_B
#define OFF_BH (2 * MAT_B)
#define OFF_BL (3 * MAT_B)
#define STAGE_B (4 * MAT_B)
#define SM_TOTAL (3 * STAGE_B)

template <int MODE>
__global__ __launch_bounds__(256, 1)
void gemm_mma(const __nv_bfloat16* __restrict__ Ahi, const __nv_bfloat16* __restrict__ Alo,
              const __nv_bfloat16* __restrict__ Bhi, const __nv_bfloat16* __restrict__ Blo,
              float* __restrict__ C,
              __half* __restrict__ Ch, __half* __restrict__ Cl) {
    extern __shared__ __align__(128) char smem[];
    const uint32_t sb = s2u(smem);
    const int tid = threadIdx.x;
    const int wid = tid >> 5;
    const int lane = tid & 31;
    const int m0 = blockIdx.y * TM;
    const int n0 = blockIdx.x * TN;
    const int wm0 = (wid >> 1) * 32;
    const int wn0 = (wid & 1) * 64;

    const int lr0 = tid >> 2;
    const int lc0 = tid & 3;
    const __nv_bfloat16* pAh = Ahi + (size_t)(m0 + lr0) * EMB + lc0 * 8;
    const __nv_bfloat16* pAl = Alo + (size_t)(m0 + lr0) * EMB + lc0 * 8;
    const __nv_bfloat16* pBh = Bhi + (size_t)(n0 + lr0) * EMB + lc0 * 8;
    const __nv_bfloat16* pBl = Blo + (size_t)(n0 + lr0) * EMB + lc0 * 8;
    const uint32_t so0 = lr0 * ROWB + lc0 * 16;

    auto load_chunk = [&](int c, int s) {
        const uint32_t base = sb + s * STAGE_B;
        const int kb = c * KB;
#pragma unroll
        for (int i = 0; i < 2; i++) {
            const uint32_t so = so0 + i * 64 * ROWB;
            const size_t go = (size_t)(64 * i) * EMB + kb;
            cpa16(base + OFF_AH + so, pAh + go);
            cpa16(base + OFF_AL + so, pAl + go);
            cpa16(base + OFF_BH + so, pBh + go);
            cpa16(base + OFF_BL + so, pBl + go);
        }
        CP_COMMIT();
    };

    float acc[2][8][4];
#pragma unroll
    for (int mf = 0; mf < 2; mf++)
#pragma unroll
        for (int nf = 0; nf < 8; nf++)
#pragma unroll
            for (int j = 0; j < 4; j++) acc[mf][nf][j] = 0.0f;

    const uint32_t aRow = wm0 + (lane & 15);
    const uint32_t aHalf = (lane >> 4) * 16;
    const uint32_t bRow = wn0 + (lane & 7);
    const uint32_t bHalf = ((lane >> 3) & 1) * 16;

    load_chunk(0, 0);
    load_chunk(1, 1);

    for (int c = 0; c < NCH; c++) {
        const int s = c - (c / 3) * 3;
        if (c + 2 < NCH) { CP_WAIT(1); } else { CP_WAIT(0); }
        __syncthreads();
        if (c + 2 < NCH) load_chunk(c + 2, s == 0 ? 2 : s - 1);

        const uint32_t st = sb + s * STAGE_B;
#pragma unroll
        for (int kk = 0; kk < 2; kk++) {
            uint32_t ah[2][4], al[2][4];
#pragma unroll
            for (int mf = 0; mf < 2; mf++) {
                const uint32_t ao = (aRow + mf * 16) * ROWB + kk * 32 + aHalf;
                ldsm4(ah[mf], st + OFF_AH + ao);
                ldsm4(al[mf], st + OFF_AL + ao);
            }
#pragma unroll
            for (int nf = 0; nf < 8; nf++) {
                uint32_t bh[2], bl[2];
                const uint32_t bo = (bRow + nf * 8) * ROWB + kk * 32 + bHalf;
                ldsm2(bh, st + OFF_BH + bo);
                ldsm2(bl, st + OFF_BL + bo);
#pragma unroll
                for (int mf = 0; mf < 2; mf++) {
                    mma_bf16(acc[mf][nf], ah[mf], bh);
                    mma_bf16(acc[mf][nf], ah[mf], bl);
                    mma_bf16(acc[mf][nf], al[mf], bh);
                }
            }
        }
    }

#pragma unroll
    for (int mf = 0; mf < 2; mf++) {
        const int mrow = m0 + wm0 + mf * 16 + (lane >> 2);
#pragma unroll
        for (int half = 0; half < 2; half++) {
            const int row = mrow + half * 8;
            const int b = row >> 11;
            const int sdx = row & (SEQL - 1);
#pragma unroll
            for (int nf = 0; nf < 8; nf++) {
                const int col = n0 + wn0 + nf * 8 + 2 * (lane & 3);
                const float c0 = acc[mf][nf][2 * half];
                const float c1 = acc[mf][nf][2 * half + 1];
                if (MODE == 0) {
                    float2 v = {c0, c1};
                    *(float2*)&C[(size_t)row * EMB + col] = v;
                } else {
                    const int h = col >> 6;
                    const int d = col & 63;
                    const size_t idx = (((size_t)(b * NH + h) * SEQL + sdx) << 6) + d;
                    if (MODE == 1) {
                        uint32_t hv, lv;
                        split2h(c0, c1, hv, lv);
                        *(uint32_t*)&Ch[idx] = hv;
                        *(uint32_t*)&Cl[idx] = lv;
                    } else {
                        __half2 hv2 = __floats2half2_rn(c0, c1);
                        *(uint32_t*)&Ch[idx] = *(uint32_t*)&hv2;
                    }
                }
            }
        }
    }
}

// ---------------- tensor-core causal flash attention (fp16 2-term) ----------
// CTA: 128 q rows, 8 warps x 16 rows. K chunks of 64.
// S = (q_hi + q_lo) . k16   (2 MMAs; only K carries fp16 rounding)
// O = (p_hi + p_lo) . v16   (2 MMAs; only V carries fp16 rounding)
#define QT 128
#define ST 64
#define KROWB 144                    // 64 fp16 cols = 128B data + 16B pad
#define KVTILE (ST * KROWB)          // 9216
#define AT_STAGE (2 * KVTILE)        // 18432: K16, V16
#define AT_SMEM (2 * AT_STAGE)       // 36864
#define QSTG (QT * KROWB)            // 18432 (Q hi then Q lo staging, reused)

__global__ __launch_bounds__(256, 1)
void attn_mma(const __half* __restrict__ Qh, const __half* __restrict__ Ql,
              const __half* __restrict__ K16, const __half* __restrict__ V16,
              __nv_bfloat16* __restrict__ Ohi, __nv_bfloat16* __restrict__ Olo) {
    extern __shared__ __align__(128) char smem[];
    const uint32_t sb = s2u(smem);
    const int tid = threadIdx.x;
    const int wid = tid >> 5;
    const int lane = tid & 31;
    const int qt = (SEQL / QT - 1) - (blockIdx.x >> 5);  // heavy tiles first
    const int bh = blockIdx.x & 31;
    const size_t hoff = (size_t)bh * SEQL * HD;

    // ---- stage Q tile (hi at sb, lo at sb+QSTG), move to registers ----
    {
        const int r = tid >> 1;
        const int cs = (tid & 1) * 4;
        const __half* qh = Qh + hoff + (size_t)(qt * QT + r) * HD + cs * 8;
        const __half* ql = Ql + hoff + (size_t)(qt * QT + r) * HD + cs * 8;
#pragma unroll
        for (int i = 0; i < 4; i++) {
            cpa16(sb + r * KROWB + (cs + i) * 16, qh + i * 8);
            cpa16(sb + QSTG + r * KROWB + (cs + i) * 16, ql + i * 8);
        }
        CP_COMMIT();
        CP_WAIT(0);
        __syncthreads();
    }
    uint32_t qah[4][4], qal[4][4];
    {
        const uint32_t qa0 = (16 * wid + (lane & 15)) * KROWB + (lane >> 4) * 16;
#pragma unroll
        for (int kk = 0; kk < 4; kk++) {
            ldsm4(qah[kk], sb + qa0 + kk * 32);
            ldsm4(qal[kk], sb + QSTG + qa0 + kk * 32);
        }
    }
    __syncthreads();  // Q staging free before KV loads overwrite it

    auto load_kv = [&](int c, int stg) {
        const uint32_t base = sb + stg * AT_STAGE;
        const size_t g0 = hoff + (size_t)(c * ST) * HD;
#pragma unroll
        for (int i = 0; i < 2; i++) {
            const int id = tid + 256 * i;
            const int r = id >> 3;
            const int sg = id & 7;
            const uint32_t so = r * KROWB + sg * 16;
            const size_t go = g0 + (size_t)r * HD + sg * 8;
            cpa16(base + so, K16 + go);
            cpa16(base + KVTILE + so, V16 + go);
        }
        CP_COMMIT();
    };

    float m_[2] = {-1e30f, -1e30f};
    float l_[2] = {0.0f, 0.0f};
    float o[8][4];
#pragma unroll
    for (int nf = 0; nf < 8; nf++)
#pragma unroll
        for (int j = 0; j < 4; j++) o[nf][j] = 0.0f;

    const int nch = 2 * qt + 2;
    load_kv(0, 0);
    if (nch > 1) load_kv(1, 1);

    const int rowa = qt * QT + 16 * wid + (lane >> 2);

    for (int c = 0; c < nch; c++) {
        if (c + 1 < nch) { CP_WAIT(1); } else { CP_WAIT(0); }
        __syncthreads();
        const uint32_t st = sb + (c & 1) * AT_STAGE;

        // ---- S = Q K^T ----
        float s[8][4];
#pragma unroll
        for (int nf = 0; nf < 8; nf++)
#pragma unroll
            for (int j = 0; j < 4; j++) s[nf][j] = 0.0f;
#pragma unroll
        for (int kk = 0; kk < 4; kk++) {
#pragma unroll
            for (int nf = 0; nf < 8; nf++) {
                uint32_t kf[2];
                const uint32_t bo =
                    (nf * 8 + (lane & 7)) * KROWB + kk * 32 + ((lane >> 3) & 1) * 16;
                ldsm2(kf, st + bo);
                mma_f16(s[nf], qah[kk], kf);
                mma_f16(s[nf], qal[kk], kf);
            }
        }

        // ---- scale + mask ----
        const bool diagc = (c >= 2 * qt);
#pragma unroll
        for (int nf = 0; nf < 8; nf++) {
#pragma unroll
            for (int j = 0; j < 4; j++) {
                float v = s[nf][j] * 0.125f;
                if (diagc) {
                    const int col = c * ST + nf * 8 + 2 * (lane & 3) + (j & 1);
                    const int row = rowa + ((j >> 1) << 3);
                    if (col > row) v = -1e30f;
                }
                s[nf][j] = v;
            }
        }

        // ---- online softmax (warp-local, quad shuffles) ----
        float rma = -1e30f, rmb = -1e30f;
#pragma unroll
        for (int nf = 0; nf < 8; nf++) {
            rma = fmaxf(rma, fmaxf(s[nf][0], s[nf][1]));
            rmb = fmaxf(rmb, fmaxf(s[nf][2], s[nf][3]));
        }
        rma = fmaxf(rma, __shfl_xor_sync(0xffffffffu, rma, 1));
        rma = fmaxf(rma, __shfl_xor_sync(0xffffffffu, rma, 2));
        rmb = fmaxf(rmb, __shfl_xor_sync(0xffffffffu, rmb, 1));
        rmb = fmaxf(rmb, __shfl_xor_sync(0xffffffffu, rmb, 2));

        const float mna = fmaxf(m_[0], rma);
        const float mnb = fmaxf(m_[1], rmb);
        const float ca = __expf(m_[0] - mna);
        const float cb = __expf(m_[1] - mnb);
        float sa = 0.0f, sbv = 0.0f;
#pragma unroll
        for (int nf = 0; nf < 8; nf++) {
            s[nf][0] = __expf(s[nf][0] - mna);
            s[nf][1] = __expf(s[nf][1] - mna);
            s[nf][2] = __expf(s[nf][2] - mnb);
            s[nf][3] = __expf(s[nf][3] - mnb);
            sa += s[nf][0] + s[nf][1];
            sbv += s[nf][2] + s[nf][3];
        }
        sa += __shfl_xor_sync(0xffffffffu, sa, 1);
        sa += __shfl_xor_sync(0xffffffffu, sa, 2);
        sbv += __shfl_xor_sync(0xffffffffu, sbv, 1);
        sbv += __shfl_xor_sync(0xffffffffu, sbv, 2);
        l_[0] = l_[0] * ca + sa;
        l_[1] = l_[1] * cb + sbv;
        m_[0] = mna;
        m_[1] = mnb;
#pragma unroll
        for (int nf = 0; nf < 8; nf++) {
            o[nf][0] *= ca;
            o[nf][1] *= ca;
            o[nf][2] *= cb;
            o[nf][3] *= cb;
        }

        // ---- O += P V (P split fp16 hi/lo in registers, V single fp16) ----
#pragma unroll
        for (int kk = 0; kk < 4; kk++) {
            uint32_t pah[4], pal[4];
            split2h(s[2 * kk][0], s[2 * kk][1], pah[0], pal[0]);
            split2h(s[2 * kk][2], s[2 * kk][3], pah[1], pal[1]);
            split2h(s[2 * kk + 1][0], s[2 * kk + 1][1], pah[2], pal[2]);
            split2h(s[2 * kk + 1][2], s[2 * kk + 1][3], pah[3], pal[3]);
#pragma unroll
            for (int nf = 0; nf < 8; nf++) {
                uint32_t vf[2];
                const uint32_t vo = (kk * 16 + (lane & 15)) * KROWB + nf * 16;
                ldsm2t(vf, st + KVTILE + vo);
                mma_f16(o[nf], pah, vf);
                mma_f16(o[nf], pal, vf);
            }
        }
        __syncthreads();  // all warps done with stage before overwrite
        if (c + 2 < nch) load_kv(c + 2, c & 1);
    }

    // ---- epilogue: normalize, split to bf16 hi/lo for w_o GEMM ----
    const int b = bh >> 4;
    const int h = bh & 15;
    const float ia = 1.0f / l_[0];
    const float ib = 1.0f / l_[1];
#pragma unroll
    for (int nf = 0; nf < 8; nf++) {
        const int e = h * 64 + nf * 8 + 2 * (lane & 3);
        uint32_t hv, lv;
        split2(o[nf][0] * ia, o[nf][1] * ia, hv, lv);
        size_t idx = (size_t)(b * SEQL + rowa) * EMB + e;
        *(uint32_t*)&Ohi[idx] = hv;
        *(uint32_t*)&Olo[idx] = lv;
        split2(o[nf][2] * ib, o[nf][3] * ib, hv, lv);
        idx = (size_t)(b * SEQL + rowa + 8) * EMB + e;
        *(uint32_t*)&Ohi[idx] = hv;
        *(uint32_t*)&Olo[idx] = lv;
    }
}

// ---------------- launch -----------------------------------------------------
extern "C" void kernel_launch(void* const* d_in, const int* in_sizes, int n_in,
                              void* d_out, int out_size) {
    const float* x = (const float*)d_in[0];
    const float* w_q = (const float*)d_in[1];
    const float* w_k = (const float*)d_in[2];
    const float* w_v = (const float*)d_in[3];
    const float* w_o = (const float*)d_in[4];
    float* out = (float*)d_out;

    __nv_bfloat16 *xhi, *xlo, *ahi, *alo;
    __half *q16h, *q16l, *k16h, *v16h;
    __nv_bfloat16 *wqh, *wql, *wkh, *wkl, *wvh, *wvl, *woh, *wol;
    cudaGetSymbolAddress((void**)&xhi, g_xhi);
    cudaGetSymbolAddress((void**)&xlo, g_xlo);
    cudaGetSymbolAddress((void**)&ahi, g_ahi);
    cudaGetSymbolAddress((void**)&alo, g_alo);
    cudaGetSymbolAddress((void**)&q16h, g_q16h);
    cudaGetSymbolAddress((void**)&q16l, g_q16l);
    cudaGetSymbolAddress((void**)&k16h, g_k16h);
    cudaGetSymbolAddress((void**)&v16h, g_v16h);
    cudaGetSymbolAddress((void**)&wqh, g_wqhi);
    cudaGetSymbolAddress((void**)&wql, g_wqlo);
    cudaGetSymbolAddress((void**)&wkh, g_wkhi);
    cudaGetSymbolAddress((void**)&wkl, g_wklo);
    cudaGetSymbolAddress((void**)&wvh, g_wvhi);
    cudaGetSymbolAddress((void**)&wvl, g_wvlo);
    cudaGetSymbolAddress((void**)&woh, g_wohi);
    cudaGetSymbolAddress((void**)&wol, g_wolo);

    cudaFuncSetAttribute(gemm_mma<0>, cudaFuncAttributeMaxDynamicSharedMemorySize, SM_TOTAL);
    cudaFuncSetAttribute(gemm_mma<1>, cudaFuncAttributeMaxDynamicSharedMemorySize, SM_TOTAL);
    cudaFuncSetAttribute(gemm_mma<2>, cudaFuncAttributeMaxDynamicSharedMemorySize, SM_TOTAL);
    cudaFuncSetAttribute(attn_mma, cudaFuncAttributeMaxDynamicSharedMemorySize, AT_SMEM);

    const int nx4 = MROWS * EMB / 4;
    const int nw4 = EMB * EMB / 4;
    cvt_split<<<nx4 / 256, 256>>>(x, xhi, xlo, nx4);
    cvt_split<<<nw4 / 256, 256>>>(w_q, wqh, wql, nw4);
    cvt_split<<<nw4 / 256, 256>>>(w_k, wkh, wkl, nw4);
    cvt_split<<<nw4 / 256, 256>>>(w_v, wvh, wvl, nw4);
    cvt_split<<<nw4 / 256, 256>>>(w_o, woh, wol, nw4);

    dim3 ggrid(EMB / TN, MROWS / TM);  // (8, 32)
    gemm_mma<1><<<ggrid, 256, SM_TOTAL>>>(xhi, xlo, wqh, wql, nullptr, q16h, q16l);
    gemm_mma<2><<<ggrid, 256, SM_TOTAL>>>(xhi, xlo, wkh, wkl, nullptr, k16h, nullptr);
    gemm_mma<2><<<ggrid, 256, SM_TOTAL>>>(xhi, xlo, wvh, wvl, nullptr, v16h, nullptr);

    attn_mma<<<(SEQL / QT) * BSZ * NH, 256, AT_SMEM>>>(q16h, q16l, k16h, v16h,
                                                       ahi, alo);

    gemm_mma<0><<<ggrid, 256, SM_TOTAL>>>(ahi, alo, woh, wol, out, nullptr, nullptr);
}

// round 9
// speedup vs baseline: 2.3234x; 1.2052x over previous
#include <cuda_runtime.h>
#include <cuda_fp16.h>
#include <cstdint>

#define BSZ 2
#define SEQL 2048
#define EMB 1024
#define NH 16
#define HD 64
#define MROWS (BSZ * SEQL)

// ---------------- scratch (__device__ globals; no allocs allowed) ----------
// A-side operands: fp16 hi + fp16 lo*1024 (exact 2-term split of fp32)
__device__ __half g_x16h[MROWS * EMB], g_x16l[MROWS * EMB];
__device__ __half g_a16h[MROWS * EMB], g_a16l[MROWS * EMB];
// B-side operands: single fp16 (one rounding source each)
__device__ __half g_wq16[EMB * EMB], g_wk16[EMB * EMB];
__device__ __half g_wv16[EMB * EMB], g_wo16[EMB * EMB];
// attention operands
__device__ __half g_q16h[BSZ * NH * SEQL * HD], g_q16l[BSZ * NH * SEQL * HD];
__device__ __half g_k16h[BSZ * NH * SEQL * HD];
__device__ __half g_v16h[BSZ * NH * SEQL * HD];

// ---------------- PTX helpers (family-compatible, sm_80-era) ----------------
__device__ __forceinline__ uint32_t s2u(const void* p) {
    uint32_t a;
    asm("{ .reg .u64 t; cvta.to.shared.u64 t, %1; cvt.u32.u64 %0, t; }"
        : "=r"(a) : "l"(p));
    return a;
}
__device__ __forceinline__ void cpa16(uint32_t d, const void* g) {
    asm volatile("cp.async.cg.shared.global [%0], [%1], 16;" :: "r"(d), "l"(g));
}
#define CP_COMMIT() asm volatile("cp.async.commit_group;" ::: "memory")
#define CP_WAIT(n) asm volatile("cp.async.wait_group %0;" :: "n"(n) : "memory")

__device__ __forceinline__ void ldsm4(uint32_t* r, uint32_t a) {
    asm volatile("ldmatrix.sync.aligned.m8n8.x4.shared.b16 {%0,%1,%2,%3}, [%4];"
                 : "=r"(r[0]), "=r"(r[1]), "=r"(r[2]), "=r"(r[3]) : "r"(a));
}
__device__ __forceinline__ void ldsm2(uint32_t* r, uint32_t a) {
    asm volatile("ldmatrix.sync.aligned.m8n8.x2.shared.b16 {%0,%1}, [%2];"
                 : "=r"(r[0]), "=r"(r[1]) : "r"(a));
}
__device__ __forceinline__ void ldsm2t(uint32_t* r, uint32_t a) {
    asm volatile("ldmatrix.sync.aligned.m8n8.x2.trans.shared.b16 {%0,%1}, [%2];"
                 : "=r"(r[0]), "=r"(r[1]) : "r"(a));
}
__device__ __forceinline__ void mma_f16(float* c, const uint32_t* a, const uint32_t* b) {
    asm volatile(
        "mma.sync.aligned.m16n8k16.row.col.f32.f16.f16.f32 "
        "{%0,%1,%2,%3}, {%4,%5,%6,%7}, {%8,%9}, {%0,%1,%2,%3};"
        : "+f"(c[0]), "+f"(c[1]), "+f"(c[2]), "+f"(c[3])
        : "r"(a[0]), "r"(a[1]), "r"(a[2]), "r"(a[3]), "r"(b[0]), "r"(b[1]));
}
// fp16 2-way split (unscaled lo): for Q fed straight into MMA
__device__ __forceinline__ void split2h(float x, float y, uint32_t& h, uint32_t& l) {
    __half2 hv = __floats2half2_rn(x, y);
    __half2 lv = __floats2half2_rn(x - __low2float(hv), y - __high2float(hv));
    h = *(uint32_t*)&hv;
    l = *(uint32_t*)&lv;
}
// fp16 2-way split with lo scaled x1024: for GEMM A-side operands
__device__ __forceinline__ void split2hs(float x, float y, uint32_t& h, uint32_t& l) {
    __half2 hv = __floats2half2_rn(x, y);
    __half2 lv = __floats2half2_rn((x - __low2float(hv)) * 1024.0f,
                                   (y - __high2float(hv)) * 1024.0f);
    h = *(uint32_t*)&hv;
    l = *(uint32_t*)&lv;
}

// ---------------- conversions ------------------------------------------------
__global__ __launch_bounds__(256) void cvt_xsplit(const float* __restrict__ in,
                                                  __half* __restrict__ hi,
                                                  __half* __restrict__ lo, int n4) {
    int i = blockIdx.x * 256 + threadIdx.x;
    if (i >= n4) return;
    float4 v = ((const float4*)in)[i];
    uint32_t h0, l0, h1, l1;
    split2hs(v.x, v.y, h0, l0);
    split2hs(v.z, v.w, h1, l1);
    ((uint32_t*)hi)[2 * i] = h0;
    ((uint32_t*)hi)[2 * i + 1] = h1;
    ((uint32_t*)lo)[2 * i] = l0;
    ((uint32_t*)lo)[2 * i + 1] = l1;
}
__global__ __launch_bounds__(256) void cvt_h(const float* __restrict__ in,
                                             __half* __restrict__ h16, int n4) {
    int i = blockIdx.x * 256 + threadIdx.x;
    if (i >= n4) return;
    float4 v = ((const float4*)in)[i];
    __half2 a = __floats2half2_rn(v.x, v.y);
    __half2 b = __floats2half2_rn(v.z, v.w);
    ((uint32_t*)h16)[2 * i] = *(uint32_t*)&a;
    ((uint32_t*)h16)[2 * i + 1] = *(uint32_t*)&b;
}

// ---------------- fp16x2 GEMM: C = (Ah + Al/1024) @ B^T ---------------------
// CTA tile 128x128, BK=32, 3-stage cp.async. 8 warps: 4(m) x 2(n).
// 2 MMAs per fragment per k16 (acc: Ah.B, acc2: Al.B), C = acc + acc2/1024.
// MODE 0: fp32 C row-major
// MODE 1: fp16 hi+lo(unscaled) scatter to [b,h,s,d]   (Q)
// MODE 2: fp16 hi only scatter to [b,h,s,d]           (K, V)
#define TM 128
#define TN 128
#define KB 32
#define NCH (EMB / KB)
#define ROWB 80
#define MAT_B (128 * ROWB)           // 10240
#define OFF_AH 0
#define OFF_AL MAT_B
#define OFF_B (2 * MAT_B)
#define STAGE_B (3 * MAT_B)          // 30720
#define SM_TOTAL (3 * STAGE_B)       // 92160

template <int MODE>
__global__ __launch_bounds__(256, 1)
void gemm_mma(const __half* __restrict__ Ah, const __half* __restrict__ Al,
              const __half* __restrict__ B16,
              float* __restrict__ C,
              __half* __restrict__ Ch, __half* __restrict__ Cl) {
    extern __shared__ __align__(128) char smem[];
    const uint32_t sb = s2u(smem);
    const int tid = threadIdx.x;
    const int wid = tid >> 5;
    const int lane = tid & 31;
    const int m0 = blockIdx.y * TM;
    const int n0 = blockIdx.x * TN;
    const int wm0 = (wid >> 1) * 32;
    const int wn0 = (wid & 1) * 64;

    const int lr0 = tid >> 2;
    const int lc0 = tid & 3;
    const __half* pAh = Ah + (size_t)(m0 + lr0) * EMB + lc0 * 8;
    const __half* pAl = Al + (size_t)(m0 + lr0) * EMB + lc0 * 8;
    const __half* pB = B16 + (size_t)(n0 + lr0) * EMB + lc0 * 8;
    const uint32_t so0 = lr0 * ROWB + lc0 * 16;

    auto load_chunk = [&](int c, int s) {
        const uint32_t base = sb + s * STAGE_B;
        const int kb = c * KB;
#pragma unroll
        for (int i = 0; i < 2; i++) {
            const uint32_t so = so0 + i * 64 * ROWB;
            const size_t go = (size_t)(64 * i) * EMB + kb;
            cpa16(base + OFF_AH + so, pAh + go);
            cpa16(base + OFF_AL + so, pAl + go);
            cpa16(base + OFF_B + so, pB + go);
        }
        CP_COMMIT();
    };

    float acc[2][8][4], acc2[2][8][4];
#pragma unroll
    for (int mf = 0; mf < 2; mf++)
#pragma unroll
        for (int nf = 0; nf < 8; nf++)
#pragma unroll
            for (int j = 0; j < 4; j++) { acc[mf][nf][j] = 0.0f; acc2[mf][nf][j] = 0.0f; }

    const uint32_t aRow = wm0 + (lane & 15);
    const uint32_t aHalf = (lane >> 4) * 16;
    const uint32_t bRow = wn0 + (lane & 7);
    const uint32_t bHalf = ((lane >> 3) & 1) * 16;

    load_chunk(0, 0);
    load_chunk(1, 1);

    for (int c = 0; c < NCH; c++) {
        const int s = c - (c / 3) * 3;
        if (c + 2 < NCH) { CP_WAIT(1); } else { CP_WAIT(0); }
        __syncthreads();
        if (c + 2 < NCH) load_chunk(c + 2, s == 0 ? 2 : s - 1);

        const uint32_t st = sb + s * STAGE_B;
#pragma unroll
        for (int kk = 0; kk < 2; kk++) {
            uint32_t ah[2][4], al[2][4];
#pragma unroll
            for (int mf = 0; mf < 2; mf++) {
                const uint32_t ao = (aRow + mf * 16) * ROWB + kk * 32 + aHalf;
                ldsm4(ah[mf], st + OFF_AH + ao);
                ldsm4(al[mf], st + OFF_AL + ao);
            }
#pragma unroll
            for (int nf = 0; nf < 8; nf++) {
                uint32_t bf[2];
                ldsm2(bf, st + OFF_B + (bRow + nf * 8) * ROWB + kk * 32 + bHalf);
#pragma unroll
                for (int mf = 0; mf < 2; mf++) {
                    mma_f16(acc[mf][nf], ah[mf], bf);
                    mma_f16(acc2[mf][nf], al[mf], bf);
                }
            }
        }
    }

#pragma unroll
    for (int mf = 0; mf < 2; mf++) {
        const int mrow = m0 + wm0 + mf * 16 + (lane >> 2);
#pragma unroll
        for (int half = 0; half < 2; half++) {
            const int row = mrow + half * 8;
            const int b = row >> 11;
            const int sdx = row & (SEQL - 1);
#pragma unroll
            for (int nf = 0; nf < 8; nf++) {
                const int col = n0 + wn0 + nf * 8 + 2 * (lane & 3);
                const float c0 =
                    acc[mf][nf][2 * half] + acc2[mf][nf][2 * half] * (1.0f / 1024.0f);
                const float c1 =
                    acc[mf][nf][2 * half + 1] + acc2[mf][nf][2 * half + 1] * (1.0f / 1024.0f);
                if (MODE == 0) {
                    float2 v = {c0, c1};
                    *(float2*)&C[(size_t)row * EMB + col] = v;
                } else {
                    const int h = col >> 6;
                    const int d = col & 63;
                    const size_t idx = (((size_t)(b * NH + h) * SEQL + sdx) << 6) + d;
                    if (MODE == 1) {
                        uint32_t hv, lv;
                        split2h(c0, c1, hv, lv);
                        *(uint32_t*)&Ch[idx] = hv;
                        *(uint32_t*)&Cl[idx] = lv;
                    } else {
                        __half2 hv2 = __floats2half2_rn(c0, c1);
                        *(uint32_t*)&Ch[idx] = *(uint32_t*)&hv2;
                    }
                }
            }
        }
    }
}

// ---------------- tensor-core causal flash attention (fp16 2-term) ----------
// CTA: 128 q rows, 8 warps x 16 rows. K chunks of 64.
// S = (q_hi + q_lo) . k16   (2 MMAs; only K carries fp16 rounding)
// O = (p_hi + p_lo) . v16   (2 MMAs; only V carries fp16 rounding)
#define QT 128
#define ST 64
#define KROWB 144
#define KVTILE (ST * KROWB)          // 9216
#define AT_STAGE (2 * KVTILE)        // 18432
#define AT_SMEM (2 * AT_STAGE)       // 36864
#define QSTG (QT * KROWB)            // 18432

__global__ __launch_bounds__(256, 1)
void attn_mma(const __half* __restrict__ Qh, const __half* __restrict__ Ql,
              const __half* __restrict__ K16, const __half* __restrict__ V16,
              __half* __restrict__ Oh, __half* __restrict__ Ol) {
    extern __shared__ __align__(128) char smem[];
    const uint32_t sb = s2u(smem);
    const int tid = threadIdx.x;
    const int wid = tid >> 5;
    const int lane = tid & 31;
    const int qt = (SEQL / QT - 1) - (blockIdx.x >> 5);  // heavy tiles first
    const int bh = blockIdx.x & 31;
    const size_t hoff = (size_t)bh * SEQL * HD;

    {
        const int r = tid >> 1;
        const int cs = (tid & 1) * 4;
        const __half* qh = Qh + hoff + (size_t)(qt * QT + r) * HD + cs * 8;
        const __half* ql = Ql + hoff + (size_t)(qt * QT + r) * HD + cs * 8;
#pragma unroll
        for (int i = 0; i < 4; i++) {
            cpa16(sb + r * KROWB + (cs + i) * 16, qh + i * 8);
            cpa16(sb + QSTG + r * KROWB + (cs + i) * 16, ql + i * 8);
        }
        CP_COMMIT();
        CP_WAIT(0);
        __syncthreads();
    }
    uint32_t qah[4][4], qal[4][4];
    {
        const uint32_t qa0 = (16 * wid + (lane & 15)) * KROWB + (lane >> 4) * 16;
#pragma unroll
        for (int kk = 0; kk < 4; kk++) {
            ldsm4(qah[kk], sb + qa0 + kk * 32);
            ldsm4(qal[kk], sb + QSTG + qa0 + kk * 32);
        }
    }
    __syncthreads();

    auto load_kv = [&](int c, int stg) {
        const uint32_t base = sb + stg * AT_STAGE;
        const size_t g0 = hoff + (size_t)(c * ST) * HD;
#pragma unroll
        for (int i = 0; i < 2; i++) {
            const int id = tid + 256 * i;
            const int r = id >> 3;
            const int sg = id & 7;
            const uint32_t so = r * KROWB + sg * 16;
            const size_t go = g0 + (size_t)r * HD + sg * 8;
            cpa16(base + so, K16 + go);
            cpa16(base + KVTILE + so, V16 + go);
        }
        CP_COMMIT();
    };

    float m_[2] = {-1e30f, -1e30f};
    float l_[2] = {0.0f, 0.0f};
    float o[8][4];
#pragma unroll
    for (int nf = 0; nf < 8; nf++)
#pragma unroll
        for (int j = 0; j < 4; j++) o[nf][j] = 0.0f;

    const int nch = 2 * qt + 2;
    load_kv(0, 0);
    if (nch > 1) load_kv(1, 1);

    const int rowa = qt * QT + 16 * wid + (lane >> 2);

    for (int c = 0; c < nch; c++) {
        if (c + 1 < nch) { CP_WAIT(1); } else { CP_WAIT(0); }
        __syncthreads();
        const uint32_t st = sb + (c & 1) * AT_STAGE;

        float s[8][4];
#pragma unroll
        for (int nf = 0; nf < 8; nf++)
#pragma unroll
            for (int j = 0; j < 4; j++) s[nf][j] = 0.0f;
#pragma unroll
        for (int kk = 0; kk < 4; kk++) {
#pragma unroll
            for (int nf = 0; nf < 8; nf++) {
                uint32_t kf[2];
                const uint32_t bo =
                    (nf * 8 + (lane & 7)) * KROWB + kk * 32 + ((lane >> 3) & 1) * 16;
                ldsm2(kf, st + bo);
                mma_f16(s[nf], qah[kk], kf);
                mma_f16(s[nf], qal[kk], kf);
            }
        }

        const bool diagc = (c >= 2 * qt);
#pragma unroll
        for (int nf = 0; nf < 8; nf++) {
#pragma unroll
            for (int j = 0; j < 4; j++) {
                float v = s[nf][j] * 0.125f;
                if (diagc) {
                    const int col = c * ST + nf * 8 + 2 * (lane & 3) + (j & 1);
                    const int row = rowa + ((j >> 1) << 3);
                    if (col > row) v = -1e30f;
                }
                s[nf][j] = v;
            }
        }

        float rma = -1e30f, rmb = -1e30f;
#pragma unroll
        for (int nf = 0; nf < 8; nf++) {
            rma = fmaxf(rma, fmaxf(s[nf][0], s[nf][1]));
            rmb = fmaxf(rmb, fmaxf(s[nf][2], s[nf][3]));
        }
        rma = fmaxf(rma, __shfl_xor_sync(0xffffffffu, rma, 1));
        rma = fmaxf(rma, __shfl_xor_sync(0xffffffffu, rma, 2));
        rmb = fmaxf(rmb, __shfl_xor_sync(0xffffffffu, rmb, 1));
        rmb = fmaxf(rmb, __shfl_xor_sync(0xffffffffu, rmb, 2));

        const float mna = fmaxf(m_[0], rma);
        const float mnb = fmaxf(m_[1], rmb);
        const float ca = __expf(m_[0] - mna);
        const float cb = __expf(m_[1] - mnb);
        float sa = 0.0f, sbv = 0.0f;
#pragma unroll
        for (int nf = 0; nf < 8; nf++) {
            s[nf][0] = __expf(s[nf][0] - mna);
            s[nf][1] = __expf(s[nf][1] - mna);
            s[nf][2] = __expf(s[nf][2] - mnb);
            s[nf][3] = __expf(s[nf][3] - mnb);
            sa += s[nf][0] + s[nf][1];
            sbv += s[nf][2] + s[nf][3];
        }
        sa += __shfl_xor_sync(0xffffffffu, sa, 1);
        sa += __shfl_xor_sync(0xffffffffu, sa, 2);
        sbv += __shfl_xor_sync(0xffffffffu, sbv, 1);
        sbv += __shfl_xor_sync(0xffffffffu, sbv, 2);
        l_[0] = l_[0] * ca + sa;
        l_[1] = l_[1] * cb + sbv;
        m_[0] = mna;
        m_[1] = mnb;
#pragma unroll
        for (int nf = 0; nf < 8; nf++) {
            o[nf][0] *= ca;
            o[nf][1] *= ca;
            o[nf][2] *= cb;
            o[nf][3] *= cb;
        }

#pragma unroll
        for (int kk = 0; kk < 4; kk++) {
            uint32_t pah[4], pal[4];
            split2h(s[2 * kk][0], s[2 * kk][1], pah[0], pal[0]);
            split2h(s[2 * kk][2], s[2 * kk][3], pah[1], pal[1]);
            split2h(s[2 * kk + 1][0], s[2 * kk + 1][1], pah[2], pal[2]);
            split2h(s[2 * kk + 1][2], s[2 * kk + 1][3], pah[3], pal[3]);
#pragma unroll
            for (int nf = 0; nf < 8; nf++) {
                uint32_t vf[2];
                const uint32_t vo = (kk * 16 + (lane & 15)) * KROWB + nf * 16;
                ldsm2t(vf, st + KVTILE + vo);
                mma_f16(o[nf], pah, vf);
                mma_f16(o[nf], pal, vf);
            }
        }
        __syncthreads();
        if (c + 2 < nch) load_kv(c + 2, c & 1);
    }

    // epilogue: normalize, emit fp16 hi + fp16 lo*1024 for the w_o GEMM
    const int b = bh >> 4;
    const int h = bh & 15;
    const float ia = 1.0f / l_[0];
    const float ib = 1.0f / l_[1];
#pragma unroll
    for (int nf = 0; nf < 8; nf++) {
        const int e = h * 64 + nf * 8 + 2 * (lane & 3);
        uint32_t hv, lv;
        split2hs(o[nf][0] * ia, o[nf][1] * ia, hv, lv);
        size_t idx = (size_t)(b * SEQL + rowa) * EMB + e;
        *(uint32_t*)&Oh[idx] = hv;
        *(uint32_t*)&Ol[idx] = lv;
        split2hs(o[nf][2] * ib, o[nf][3] * ib, hv, lv);
        idx = (size_t)(b * SEQL + rowa + 8) * EMB + e;
        *(uint32_t*)&Oh[idx] = hv;
        *(uint32_t*)&Ol[idx] = lv;
    }
}

// ---------------- launch -----------------------------------------------------
extern "C" void kernel_launch(void* const* d_in, const int* in_sizes, int n_in,
                              void* d_out, int out_size) {
    const float* x = (const float*)d_in[0];
    const float* w_q = (const float*)d_in[1];
    const float* w_k = (const float*)d_in[2];
    const float* w_v = (const float*)d_in[3];
    const float* w_o = (const float*)d_in[4];
    float* out = (float*)d_out;

    __half *x16h, *x16l, *a16h, *a16l;
    __half *wq16, *wk16, *wv16, *wo16;
    __half *q16h, *q16l, *k16h, *v16h;
    cudaGetSymbolAddress((void**)&x16h, g_x16h);
    cudaGetSymbolAddress((void**)&x16l, g_x16l);
    cudaGetSymbolAddress((void**)&a16h, g_a16h);
    cudaGetSymbolAddress((void**)&a16l, g_a16l);
    cudaGetSymbolAddress((void**)&wq16, g_wq16);
    cudaGetSymbolAddress((void**)&wk16, g_wk16);
    cudaGetSymbolAddress((void**)&wv16, g_wv16);
    cudaGetSymbolAddress((void**)&wo16, g_wo16);
    cudaGetSymbolAddress((void**)&q16h, g_q16h);
    cudaGetSymbolAddress((void**)&q16l, g_q16l);
    cudaGetSymbolAddress((void**)&k16h, g_k16h);
    cudaGetSymbolAddress((void**)&v16h, g_v16h);

    cudaFuncSetAttribute(gemm_mma<0>, cudaFuncAttributeMaxDynamicSharedMemorySize, SM_TOTAL);
    cudaFuncSetAttribute(gemm_mma<1>, cudaFuncAttributeMaxDynamicSharedMemorySize, SM_TOTAL);
    cudaFuncSetAttribute(gemm_mma<2>, cudaFuncAttributeMaxDynamicSharedMemorySize, SM_TOTAL);
    cudaFuncSetAttribute(attn_mma, cudaFuncAttributeMaxDynamicSharedMemorySize, AT_SMEM);

    const int nx4 = MROWS * EMB / 4;
    const int nw4 = EMB * EMB / 4;
    cvt_xsplit<<<nx4 / 256, 256>>>(x, x16h, x16l, nx4);
    cvt_h<<<nw4 / 256, 256>>>(w_q, wq16, nw4);
    cvt_h<<<nw4 / 256, 256>>>(w_k, wk16, nw4);
    cvt_h<<<nw4 / 256, 256>>>(w_v, wv16, nw4);
    cvt_h<<<nw4 / 256, 256>>>(w_o, wo16, nw4);

    dim3 ggrid(EMB / TN, MROWS / TM);  // (8, 32)
    gemm_mma<1><<<ggrid, 256, SM_TOTAL>>>(x16h, x16l, wq16, nullptr, q16h, q16l);
    gemm_mma<2><<<ggrid, 256, SM_TOTAL>>>(x16h, x16l, wk16, nullptr, k16h, nullptr);
    gemm_mma<2><<<ggrid, 256, SM_TOTAL>>>(x16h, x16l, wv16, nullptr, v16h, nullptr);

    attn_mma<<<(SEQL / QT) * BSZ * NH, 256, AT_SMEM>>>(q16h, q16l, k16h, v16h,
                                                       a16h, a16l);

    gemm_mma<0><<<ggrid, 256, SM_TOTAL>>>(a16h, a16l, wo16, out, nullptr, nullptr);
}

// round 11
// speedup vs baseline: 2.6576x; 1.1438x over previous
#include <cuda_runtime.h>
#include <cuda_fp16.h>
#include <cstdint>

#define BSZ 2
#define SEQL 2048
#define EMB 1024
#define NH 16
#define HD 64
#define MROWS (BSZ * SEQL)

// ---------------- scratch (__device__ globals; no allocs allowed) ----------
__device__ __half g_x16[MROWS * EMB];
__device__ __half g_a16[MROWS * EMB];
__device__ __half g_wq16[EMB * EMB], g_wk16[EMB * EMB];
__device__ __half g_wv16[EMB * EMB], g_wo16[EMB * EMB];
__device__ __half g_q16[BSZ * NH * SEQL * HD];
__device__ __half g_k16[BSZ * NH * SEQL * HD];
__device__ __half g_v16[BSZ * NH * SEQL * HD];

// ---------------- PTX helpers (family-compatible, sm_80-era) ----------------
__device__ __forceinline__ uint32_t s2u(const void* p) {
    uint32_t a;
    asm("{ .reg .u64 t; cvta.to.shared.u64 t, %1; cvt.u32.u64 %0, t; }"
        : "=r"(a) : "l"(p));
    return a;
}
__device__ __forceinline__ void cpa16(uint32_t d, const void* g) {
    asm volatile("cp.async.cg.shared.global [%0], [%1], 16;" :: "r"(d), "l"(g));
}
#define CP_COMMIT() asm volatile("cp.async.commit_group;" ::: "memory")
#define CP_WAIT(n) asm volatile("cp.async.wait_group %0;" :: "n"(n) : "memory")

__device__ __forceinline__ void ldsm4(uint32_t* r, uint32_t a) {
    asm volatile("ldmatrix.sync.aligned.m8n8.x4.shared.b16 {%0,%1,%2,%3}, [%4];"
                 : "=r"(r[0]), "=r"(r[1]), "=r"(r[2]), "=r"(r[3]) : "r"(a));
}
__device__ __forceinline__ void ldsm2(uint32_t* r, uint32_t a) {
    asm volatile("ldmatrix.sync.aligned.m8n8.x2.shared.b16 {%0,%1}, [%2];"
                 : "=r"(r[0]), "=r"(r[1]) : "r"(a));
}
__device__ __forceinline__ void ldsm2t(uint32_t* r, uint32_t a) {
    asm volatile("ldmatrix.sync.aligned.m8n8.x2.trans.shared.b16 {%0,%1}, [%2];"
                 : "=r"(r[0]), "=r"(r[1]) : "r"(a));
}
__device__ __forceinline__ void mma_f16(float* c, const uint32_t* a, const uint32_t* b) {
    asm volatile(
        "mma.sync.aligned.m16n8k16.row.col.f32.f16.f16.f32 "
        "{%0,%1,%2,%3}, {%4,%5,%6,%7}, {%8,%9}, {%0,%1,%2,%3};"
        : "+f"(c[0]), "+f"(c[1]), "+f"(c[2]), "+f"(c[3])
        : "r"(a[0]), "r"(a[1]), "r"(a[2]), "r"(a[3]), "r"(b[0]), "r"(b[1]));
}

// ---------------- all fp32 -> fp16 conversions in ONE kernel ----------------
// blocks [0,4096): x (1Mi float4); then 4 weights, 1024 blocks each.
__global__ __launch_bounds__(256) void cvt_all(
    const float* __restrict__ x, const float* __restrict__ wq,
    const float* __restrict__ wk, const float* __restrict__ wv,
    const float* __restrict__ wo,
    __half* __restrict__ x16, __half* __restrict__ wq16,
    __half* __restrict__ wk16, __half* __restrict__ wv16,
    __half* __restrict__ wo16) {
    const int b = blockIdx.x;
    const float* in;
    __half* out;
    int i;
    if (b < 4096) {
        in = x; out = x16; i = b * 256 + threadIdx.x;
    } else {
        const int w = (b - 4096) >> 10;
        i = ((b - 4096) & 1023) * 256 + threadIdx.x;
        in = (w == 0) ? wq : (w == 1) ? wk : (w == 2) ? wv : wo;
        out = (w == 0) ? wq16 : (w == 1) ? wk16 : (w == 2) ? wv16 : wo16;
    }
    float4 v = ((const float4*)in)[i];
    __half2 a = __floats2half2_rn(v.x, v.y);
    __half2 c = __floats2half2_rn(v.z, v.w);
    ((uint32_t*)out)[2 * i] = *(uint32_t*)&a;
    ((uint32_t*)out)[2 * i + 1] = *(uint32_t*)&c;
}

// ---------------- fp16 GEMM: C = A @ B^T ------------------------------------
// CTA tile 128x128, BK=32, 3-stage cp.async. 8 warps: 4(m) x 2(n).
// 1 MMA per fragment per k16.
// MODE 0: fp32 C row-major; MODE 1: fp16 scatter to [b,h,s,d]
#define TM 128
#define TN 128
#define KB 32
#define NCH (EMB / KB)
#define ROWB 80
#define MAT_B (128 * ROWB)           // 10240
#define OFF_A 0
#define OFF_B MAT_B
#define STAGE_B (2 * MAT_B)          // 20480
#define SM_TOTAL (3 * STAGE_B)       // 61440

template <int MODE>
__global__ __launch_bounds__(256, 2)
void gemm_mma(const __half* __restrict__ A16, const __half* __restrict__ B16,
              float* __restrict__ C, __half* __restrict__ Ch) {
    extern __shared__ __align__(128) char smem[];
    const uint32_t sb = s2u(smem);
    const int tid = threadIdx.x;
    const int wid = tid >> 5;
    const int lane = tid & 31;
    const int m0 = blockIdx.y * TM;
    const int n0 = blockIdx.x * TN;
    const int wm0 = (wid >> 1) * 32;
    const int wn0 = (wid & 1) * 64;

    const int lr0 = tid >> 2;
    const int lc0 = tid & 3;
    const __half* pA = A16 + (size_t)(m0 + lr0) * EMB + lc0 * 8;
    const __half* pB = B16 + (size_t)(n0 + lr0) * EMB + lc0 * 8;
    const uint32_t so0 = lr0 * ROWB + lc0 * 16;

    auto load_chunk = [&](int c, int s) {
        const uint32_t base = sb + s * STAGE_B;
        const int kb = c * KB;
#pragma unroll
        for (int i = 0; i < 2; i++) {
            const uint32_t so = so0 + i * 64 * ROWB;
            const size_t go = (size_t)(64 * i) * EMB + kb;
            cpa16(base + OFF_A + so, pA + go);
            cpa16(base + OFF_B + so, pB + go);
        }
        CP_COMMIT();
    };

    float acc[2][8][4];
#pragma unroll
    for (int mf = 0; mf < 2; mf++)
#pragma unroll
        for (int nf = 0; nf < 8; nf++)
#pragma unroll
            for (int j = 0; j < 4; j++) acc[mf][nf][j] = 0.0f;

    const uint32_t aRow = wm0 + (lane & 15);
    const uint32_t aHalf = (lane >> 4) * 16;
    const uint32_t bRow = wn0 + (lane & 7);
    const uint32_t bHalf = ((lane >> 3) & 1) * 16;

    load_chunk(0, 0);
    load_chunk(1, 1);

    for (int c = 0; c < NCH; c++) {
        const int s = c - (c / 3) * 3;
        if (c + 2 < NCH) { CP_WAIT(1); } else { CP_WAIT(0); }
        __syncthreads();
        if (c + 2 < NCH) load_chunk(c + 2, s == 0 ? 2 : s - 1);

        const uint32_t st = sb + s * STAGE_B;
#pragma unroll
        for (int kk = 0; kk < 2; kk++) {
            uint32_t ah[2][4];
#pragma unroll
            for (int mf = 0; mf < 2; mf++)
                ldsm4(ah[mf], st + OFF_A + (aRow + mf * 16) * ROWB + kk * 32 + aHalf);
#pragma unroll
            for (int nf = 0; nf < 8; nf++) {
                uint32_t bf[2];
                ldsm2(bf, st + OFF_B + (bRow + nf * 8) * ROWB + kk * 32 + bHalf);
#pragma unroll
                for (int mf = 0; mf < 2; mf++) mma_f16(acc[mf][nf], ah[mf], bf);
            }
        }
    }

#pragma unroll
    for (int mf = 0; mf < 2; mf++) {
        const int mrow = m0 + wm0 + mf * 16 + (lane >> 2);
#pragma unroll
        for (int half = 0; half < 2; half++) {
            const int row = mrow + half * 8;
            const int b = row >> 11;
            const int sdx = row & (SEQL - 1);
#pragma unroll
            for (int nf = 0; nf < 8; nf++) {
                const int col = n0 + wn0 + nf * 8 + 2 * (lane & 3);
                const float c0 = acc[mf][nf][2 * half];
                const float c1 = acc[mf][nf][2 * half + 1];
                if (MODE == 0) {
                    float2 v = {c0, c1};
                    *(float2*)&C[(size_t)row * EMB + col] = v;
                } else {
                    const int h = col >> 6;
                    const int d = col & 63;
                    const size_t idx = (((size_t)(b * NH + h) * SEQL + sdx) << 6) + d;
                    __half2 hv2 = __floats2half2_rn(c0, c1);
                    *(uint32_t*)&Ch[idx] = *(uint32_t*)&hv2;
                }
            }
        }
    }
}

// ---------------- tensor-core causal flash attention (single fp16) ----------
// CTA: 128 q rows, 8 warps x 16 rows. K chunks of 64.
// S = q16 . k16 (1 MMA), O = p16 . v16 (1 MMA).
#define QT 128
#define ST 64
#define KROWB 144
#define KVTILE (ST * KROWB)          // 9216
#define AT_STAGE (2 * KVTILE)        // 18432
#define AT_SMEM (2 * AT_STAGE)       // 36864
#define QSTG (QT * KROWB)            // 18432

__global__ __launch_bounds__(256, 1)
void attn_mma(const __half* __restrict__ Q16, const __half* __restrict__ K16,
              const __half* __restrict__ V16, __half* __restrict__ O16) {
    extern __shared__ __align__(128) char smem[];
    const uint32_t sb = s2u(smem);
    const int tid = threadIdx.x;
    const int wid = tid >> 5;
    const int lane = tid & 31;
    const int qt = (SEQL / QT - 1) - (blockIdx.x >> 5);  // heavy tiles first
    const int bh = blockIdx.x & 31;
    const size_t hoff = (size_t)bh * SEQL * HD;

    // ---- stage Q tile, move to registers ----
    {
        const int r = tid >> 1;
        const int cs = (tid & 1) * 4;
        const __half* qp = Q16 + hoff + (size_t)(qt * QT + r) * HD + cs * 8;
#pragma unroll
        for (int i = 0; i < 4; i++)
            cpa16(sb + r * KROWB + (cs + i) * 16, qp + i * 8);
        CP_COMMIT();
        CP_WAIT(0);
        __syncthreads();
    }
    uint32_t qa[4][4];
    {
        const uint32_t qa0 = (16 * wid + (lane & 15)) * KROWB + (lane >> 4) * 16;
#pragma unroll
        for (int kk = 0; kk < 4; kk++) ldsm4(qa[kk], sb + qa0 + kk * 32);
    }
    __syncthreads();

    auto load_kv = [&](int c, int stg) {
        const uint32_t base = sb + stg * AT_STAGE;
        const size_t g0 = hoff + (size_t)(c * ST) * HD;
#pragma unroll
        for (int i = 0; i < 2; i++) {
            const int id = tid + 256 * i;
            const int r = id >> 3;
            const int sg = id & 7;
            const uint32_t so = r * KROWB + sg * 16;
            const size_t go = g0 + (size_t)r * HD + sg * 8;
            cpa16(base + so, K16 + go);
            cpa16(base + KVTILE + so, V16 + go);
        }
        CP_COMMIT();
    };

    float m_[2] = {-1e30f, -1e30f};
    float l_[2] = {0.0f, 0.0f};
    float o[8][4];
#pragma unroll
    for (int nf = 0; nf < 8; nf++)
#pragma unroll
        for (int j = 0; j < 4; j++) o[nf][j] = 0.0f;

    const int nch = 2 * qt + 2;
    load_kv(0, 0);
    if (nch > 1) load_kv(1, 1);

    const int rowa = qt * QT + 16 * wid + (lane >> 2);

    for (int c = 0; c < nch; c++) {
        if (c + 1 < nch) { CP_WAIT(1); } else { CP_WAIT(0); }
        __syncthreads();
        const uint32_t st = sb + (c & 1) * AT_STAGE;

        // ---- S = Q K^T ----
        float s[8][4];
#pragma unroll
        for (int nf = 0; nf < 8; nf++)
#pragma unroll
            for (int j = 0; j < 4; j++) s[nf][j] = 0.0f;
#pragma unroll
        for (int kk = 0; kk < 4; kk++) {
#pragma unroll
            for (int nf = 0; nf < 8; nf++) {
                uint32_t kf[2];
                const uint32_t bo =
                    (nf * 8 + (lane & 7)) * KROWB + kk * 32 + ((lane >> 3) & 1) * 16;
                ldsm2(kf, st + bo);
                mma_f16(s[nf], qa[kk], kf);
            }
        }

        // ---- scale + mask ----
        const bool diagc = (c >= 2 * qt);
#pragma unroll
        for (int nf = 0; nf < 8; nf++) {
#pragma unroll
            for (int j = 0; j < 4; j++) {
                float v = s[nf][j] * 0.125f;
                if (diagc) {
                    const int col = c * ST + nf * 8 + 2 * (lane & 3) + (j & 1);
                    const int row = rowa + ((j >> 1) << 3);
                    if (col > row) v = -1e30f;
                }
                s[nf][j] = v;
            }
        }

        // ---- online softmax (warp-local, quad shuffles) ----
        float rma = -1e30f, rmb = -1e30f;
#pragma unroll
        for (int nf = 0; nf < 8; nf++) {
            rma = fmaxf(rma, fmaxf(s[nf][0], s[nf][1]));
            rmb = fmaxf(rmb, fmaxf(s[nf][2], s[nf][3]));
        }
        rma = fmaxf(rma, __shfl_xor_sync(0xffffffffu, rma, 1));
        rma = fmaxf(rma, __shfl_xor_sync(0xffffffffu, rma, 2));
        rmb = fmaxf(rmb, __shfl_xor_sync(0xffffffffu, rmb, 1));
        rmb = fmaxf(rmb, __shfl_xor_sync(0xffffffffu, rmb, 2));

        const float mna = fmaxf(m_[0], rma);
        const float mnb = fmaxf(m_[1], rmb);
        const float ca = __expf(m_[0] - mna);
        const float cb = __expf(m_[1] - mnb);
        float sa = 0.0f, sbv = 0.0f;
#pragma unroll
        for (int nf = 0; nf < 8; nf++) {
            s[nf][0] = __expf(s[nf][0] - mna);
            s[nf][1] = __expf(s[nf][1] - mna);
            s[nf][2] = __expf(s[nf][2] - mnb);
            s[nf][3] = __expf(s[nf][3] - mnb);
            sa += s[nf][0] + s[nf][1];
            sbv += s[nf][2] + s[nf][3];
        }
        sa += __shfl_xor_sync(0xffffffffu, sa, 1);
        sa += __shfl_xor_sync(0xffffffffu, sa, 2);
        sbv += __shfl_xor_sync(0xffffffffu, sbv, 1);
        sbv += __shfl_xor_sync(0xffffffffu, sbv, 2);
        l_[0] = l_[0] * ca + sa;
        l_[1] = l_[1] * cb + sbv;
        m_[0] = mna;
        m_[1] = mnb;
#pragma unroll
        for (int nf = 0; nf < 8; nf++) {
            o[nf][0] *= ca;
            o[nf][1] *= ca;
            o[nf][2] *= cb;
            o[nf][3] *= cb;
        }

        // ---- O += P V (single fp16 P) ----
#pragma unroll
        for (int kk = 0; kk < 4; kk++) {
            uint32_t ph[4];
            __half2 t0 = __floats2half2_rn(s[2 * kk][0], s[2 * kk][1]);
            __half2 t1 = __floats2half2_rn(s[2 * kk][2], s[2 * kk][3]);
            __half2 t2 = __floats2half2_rn(s[2 * kk + 1][0], s[2 * kk + 1][1]);
            __half2 t3 = __floats2half2_rn(s[2 * kk + 1][2], s[2 * kk + 1][3]);
            ph[0] = *(uint32_t*)&t0;
            ph[1] = *(uint32_t*)&t1;
            ph[2] = *(uint32_t*)&t2;
            ph[3] = *(uint32_t*)&t3;
#pragma unroll
            for (int nf = 0; nf < 8; nf++) {
                uint32_t vf[2];
                const uint32_t vo = (kk * 16 + (lane & 15)) * KROWB + nf * 16;
                ldsm2t(vf, st + KVTILE + vo);
                mma_f16(o[nf], ph, vf);
            }
        }
        __syncthreads();
        if (c + 2 < nch) load_kv(c + 2, c & 1);
    }

    // ---- epilogue: normalize, emit fp16 for the w_o GEMM ----
    const int b = bh >> 4;
    const int h = bh & 15;
    const float ia = 1.0f / l_[0];
    const float ib = 1.0f / l_[1];
#pragma unroll
    for (int nf = 0; nf < 8; nf++) {
        const int e = h * 64 + nf * 8 + 2 * (lane & 3);
        __half2 hv = __floats2half2_rn(o[nf][0] * ia, o[nf][1] * ia);
        size_t idx = (size_t)(b * SEQL + rowa) * EMB + e;
        *(uint32_t*)&O16[idx] = *(uint32_t*)&hv;
        hv = __floats2half2_rn(o[nf][2] * ib, o[nf][3] * ib);
        idx = (size_t)(b * SEQL + rowa + 8) * EMB + e;
        *(uint32_t*)&O16[idx] = *(uint32_t*)&hv;
    }
}

// ---------------- launch -----------------------------------------------------
extern "C" void kernel_launch(void* const* d_in, const int* in_sizes, int n_in,
                              void* d_out, int out_size) {
    const float* x = (const float*)d_in[0];
    const float* w_q = (const float*)d_in[1];
    const float* w_k = (const float*)d_in[2];
    const float* w_v = (const float*)d_in[3];
    const float* w_o = (const float*)d_in[4];
    float* out = (float*)d_out;

    __half *x16, *a16, *wq16, *wk16, *wv16, *wo16, *q16, *k16, *v16;
    cudaGetSymbolAddress((void**)&x16, g_x16);
    cudaGetSymbolAddress((void**)&a16, g_a16);
    cudaGetSymbolAddress((void**)&wq16, g_wq16);
    cudaGetSymbolAddress((void**)&wk16, g_wk16);
    cudaGetSymbolAddress((void**)&wv16, g_wv16);
    cudaGetSymbolAddress((void**)&wo16, g_wo16);
    cudaGetSymbolAddress((void**)&q16, g_q16);
    cudaGetSymbolAddress((void**)&k16, g_k16);
    cudaGetSymbolAddress((void**)&v16, g_v16);

    cudaFuncSetAttribute(gemm_mma<0>, cudaFuncAttributeMaxDynamicSharedMemorySize, SM_TOTAL);
    cudaFuncSetAttribute(gemm_mma<1>, cudaFuncAttributeMaxDynamicSharedMemorySize, SM_TOTAL);
    cudaFuncSetAttribute(attn_mma, cudaFuncAttributeMaxDynamicSharedMemorySize, AT_SMEM);

    cvt_all<<<4096 + 4 * 1024, 256>>>(x, w_q, w_k, w_v, w_o,
                                      x16, wq16, wk16, wv16, wo16);

    dim3 ggrid(EMB / TN, MROWS / TM);  // (8, 32)
    gemm_mma<1><<<ggrid, 256, SM_TOTAL>>>(x16, wq16, nullptr, q16);
    gemm_mma<1><<<ggrid, 256, SM_TOTAL>>>(x16, wk16, nullptr, k16);
    gemm_mma<1><<<ggrid, 256, SM_TOTAL>>>(x16, wv16, nullptr, v16);

    attn_mma<<<(SEQL / QT) * BSZ * NH, 256, AT_SMEM>>>(q16, k16, v16, a16);

    gemm_mma<0><<<ggrid, 256, SM_TOTAL>>>(a16, wo16, out, nullptr);
}

// round 12
// speedup vs baseline: 3.5999x; 1.3545x over previous
#include <cuda_runtime.h>
#include <cuda_fp16.h>
#include <cstdint>

#define BSZ 2
#define SEQL 2048
#define EMB 1024
#define NH 16
#define HD 64
#define MROWS (BSZ * SEQL)

// ---------------- scratch (__device__ globals; no allocs allowed) ----------
__device__ __half g_x16[MROWS * EMB];
__device__ __half g_a16[MROWS * EMB];
__device__ __half g_wq16[EMB * EMB], g_wk16[EMB * EMB];
__device__ __half g_wv16[EMB * EMB], g_wo16[EMB * EMB];
__device__ __half g_q16[BSZ * NH * SEQL * HD];
__device__ __half g_k16[BSZ * NH * SEQL * HD];
__device__ __half g_v16[BSZ * NH * SEQL * HD];

// ---------------- PTX helpers (family-compatible, sm_80-era) ----------------
__device__ __forceinline__ uint32_t s2u(const void* p) {
    uint32_t a;
    asm("{ .reg .u64 t; cvta.to.shared.u64 t, %1; cvt.u32.u64 %0, t; }"
        : "=r"(a) : "l"(p));
    return a;
}
__device__ __forceinline__ void cpa16(uint32_t d, const void* g) {
    asm volatile("cp.async.cg.shared.global [%0], [%1], 16;" :: "r"(d), "l"(g));
}
#define CP_COMMIT() asm volatile("cp.async.commit_group;" ::: "memory")
#define CP_WAIT(n) asm volatile("cp.async.wait_group %0;" :: "n"(n) : "memory")

__device__ __forceinline__ void ldsm4(uint32_t* r, uint32_t a) {
    asm volatile("ldmatrix.sync.aligned.m8n8.x4.shared.b16 {%0,%1,%2,%3}, [%4];"
                 : "=r"(r[0]), "=r"(r[1]), "=r"(r[2]), "=r"(r[3]) : "r"(a));
}
__device__ __forceinline__ void ldsm2t(uint32_t* r, uint32_t a) {
    asm volatile("ldmatrix.sync.aligned.m8n8.x2.trans.shared.b16 {%0,%1}, [%2];"
                 : "=r"(r[0]), "=r"(r[1]) : "r"(a));
}
__device__ __forceinline__ void mma_f16(float* c, const uint32_t* a, const uint32_t* b) {
    asm volatile(
        "mma.sync.aligned.m16n8k16.row.col.f32.f16.f16.f32 "
        "{%0,%1,%2,%3}, {%4,%5,%6,%7}, {%8,%9}, {%0,%1,%2,%3};"
        : "+f"(c[0]), "+f"(c[1]), "+f"(c[2]), "+f"(c[3])
        : "r"(a[0]), "r"(a[1]), "r"(a[2]), "r"(a[3]), "r"(b[0]), "r"(b[1]));
}

// ---------------- all fp32 -> fp16 conversions in ONE kernel ----------------
__global__ __launch_bounds__(256) void cvt_all(
    const float* __restrict__ x, const float* __restrict__ wq,
    const float* __restrict__ wk, const float* __restrict__ wv,
    const float* __restrict__ wo,
    __half* __restrict__ x16, __half* __restrict__ wq16,
    __half* __restrict__ wk16, __half* __restrict__ wv16,
    __half* __restrict__ wo16) {
    const int b = blockIdx.x;
    const float* in;
    __half* out;
    int i;
    if (b < 4096) {
        in = x; out = x16; i = b * 256 + threadIdx.x;
    } else {
        const int w = (b - 4096) >> 10;
        i = ((b - 4096) & 1023) * 256 + threadIdx.x;
        in = (w == 0) ? wq : (w == 1) ? wk : (w == 2) ? wv : wo;
        out = (w == 0) ? wq16 : (w == 1) ? wk16 : (w == 2) ? wv16 : wo16;
    }
    float4 v = ((const float4*)in)[i];
    __half2 a = __floats2half2_rn(v.x, v.y);
    __half2 c = __floats2half2_rn(v.z, v.w);
    ((uint32_t*)out)[2 * i] = *(uint32_t*)&a;
    ((uint32_t*)out)[2 * i + 1] = *(uint32_t*)&c;
}

// ---------------- fp16 GEMM: C = A @ B^T ------------------------------------
// CTA tile 128x128, BK=64, 2-stage cp.async. 8 warps: 4(m) x 2(n).
// Per k16: 2 ldsm4 (A, 2 frags) + 4 ldsm4 (B, 8 frags) + 16 MMAs.
// MODE 0: fp32 C row-major; MODE 1: fp16 scatter to [b,h,s,d]
#define TM 128
#define TN 128
#define KB 64
#define NCH (EMB / KB)               // 16
#define ROWB 144                     // 64 halfs = 128B data + 16B pad
#define MAT_B (128 * ROWB)           // 18432
#define OFF_A 0
#define OFF_B MAT_B
#define STAGE_B (2 * MAT_B)          // 36864
#define SM_TOTAL (2 * STAGE_B)       // 73728

template <int MODE>
__global__ __launch_bounds__(256, 2)
void gemm_mma(const __half* __restrict__ A16, const __half* __restrict__ B16,
              float* __restrict__ C, __half* __restrict__ Ch) {
    extern __shared__ __align__(128) char smem[];
    const uint32_t sb = s2u(smem);
    const int tid = threadIdx.x;
    const int wid = tid >> 5;
    const int lane = tid & 31;
    const int m0 = blockIdx.y * TM;
    const int n0 = blockIdx.x * TN;
    const int wm0 = (wid >> 1) * 32;
    const int wn0 = (wid & 1) * 64;

    // load geometry: thread covers row lr, 4 x 16B chunks starting at lc
    const int lr = tid >> 1;           // 0..127
    const int lc = (tid & 1) * 4;      // chunk base 0 or 4
    const __half* pA = A16 + (size_t)(m0 + lr) * EMB + lc * 8;
    const __half* pB = B16 + (size_t)(n0 + lr) * EMB + lc * 8;
    const uint32_t so0 = lr * ROWB + lc * 16;

    auto load_chunk = [&](int c, int s) {
        const uint32_t base = sb + s * STAGE_B;
        const int kb = c * KB;
#pragma unroll
        for (int i = 0; i < 4; i++) {
            cpa16(base + OFF_A + so0 + i * 16, pA + kb + i * 8);
            cpa16(base + OFF_B + so0 + i * 16, pB + kb + i * 8);
        }
        CP_COMMIT();
    };

    float acc[2][8][4];
#pragma unroll
    for (int mf = 0; mf < 2; mf++)
#pragma unroll
        for (int nf = 0; nf < 8; nf++)
#pragma unroll
            for (int j = 0; j < 4; j++) acc[mf][nf][j] = 0.0f;

    const uint32_t aRow = wm0 + (lane & 15);
    const uint32_t xHalf = (lane >> 4) * 16;
    const uint32_t bRow = wn0 + (lane & 15);

    load_chunk(0, 0);

    for (int c = 0; c < NCH; c++) {
        CP_WAIT(0);
        __syncthreads();
        if (c + 1 < NCH) load_chunk(c + 1, (c + 1) & 1);

        const uint32_t st = sb + (c & 1) * STAGE_B;
#pragma unroll
        for (int kk = 0; kk < 4; kk++) {
            uint32_t ah[2][4];
#pragma unroll
            for (int mf = 0; mf < 2; mf++)
                ldsm4(ah[mf], st + OFF_A + (aRow + mf * 16) * ROWB + kk * 32 + xHalf);
#pragma unroll
            for (int nfp = 0; nfp < 4; nfp++) {
                uint32_t bq[4];
                ldsm4(bq, st + OFF_B + (bRow + nfp * 16) * ROWB + kk * 32 + xHalf);
                uint32_t be[2] = {bq[0], bq[2]};
                uint32_t bo[2] = {bq[1], bq[3]};
#pragma unroll
                for (int mf = 0; mf < 2; mf++) {
                    mma_f16(acc[mf][2 * nfp], ah[mf], be);
                    mma_f16(acc[mf][2 * nfp + 1], ah[mf], bo);
                }
            }
        }
    }

#pragma unroll
    for (int mf = 0; mf < 2; mf++) {
        const int mrow = m0 + wm0 + mf * 16 + (lane >> 2);
#pragma unroll
        for (int half = 0; half < 2; half++) {
            const int row = mrow + half * 8;
            const int b = row >> 11;
            const int sdx = row & (SEQL - 1);
#pragma unroll
            for (int nf = 0; nf < 8; nf++) {
                const int col = n0 + wn0 + nf * 8 + 2 * (lane & 3);
                const float c0 = acc[mf][nf][2 * half];
                const float c1 = acc[mf][nf][2 * half + 1];
                if (MODE == 0) {
                    float2 v = {c0, c1};
                    *(float2*)&C[(size_t)row * EMB + col] = v;
                } else {
                    const int h = col >> 6;
                    const int d = col & 63;
                    const size_t idx = (((size_t)(b * NH + h) * SEQL + sdx) << 6) + d;
                    __half2 hv2 = __floats2half2_rn(c0, c1);
                    *(uint32_t*)&Ch[idx] = *(uint32_t*)&hv2;
                }
            }
        }
    }
}

// ---------------- tensor-core causal flash attention (single fp16) ----------
// CTA: 128 q rows, 8 warps x 16 rows. K chunks of 64.
// S = q16 . k16 (K via ldsm4 pairs), O = p16 . v16.
#define QT 128
#define ST 64
#define KROWB 144
#define KVTILE (ST * KROWB)          // 9216
#define AT_STAGE (2 * KVTILE)        // 18432
#define AT_SMEM (2 * AT_STAGE)       // 36864
#define QSTG (QT * KROWB)            // 18432

__global__ __launch_bounds__(256, 1)
void attn_mma(const __half* __restrict__ Q16, const __half* __restrict__ K16,
              const __half* __restrict__ V16, __half* __restrict__ O16) {
    extern __shared__ __align__(128) char smem[];
    const uint32_t sb = s2u(smem);
    const int tid = threadIdx.x;
    const int wid = tid >> 5;
    const int lane = tid & 31;
    const int qt = (SEQL / QT - 1) - (blockIdx.x >> 5);  // heavy tiles first
    const int bh = blockIdx.x & 31;
    const size_t hoff = (size_t)bh * SEQL * HD;

    // ---- stage Q tile, move to registers ----
    {
        const int r = tid >> 1;
        const int cs = (tid & 1) * 4;
        const __half* qp = Q16 + hoff + (size_t)(qt * QT + r) * HD + cs * 8;
#pragma unroll
        for (int i = 0; i < 4; i++)
            cpa16(sb + r * KROWB + (cs + i) * 16, qp + i * 8);
        CP_COMMIT();
        CP_WAIT(0);
        __syncthreads();
    }
    uint32_t qa[4][4];
    {
        const uint32_t qa0 = (16 * wid + (lane & 15)) * KROWB + (lane >> 4) * 16;
#pragma unroll
        for (int kk = 0; kk < 4; kk++) ldsm4(qa[kk], sb + qa0 + kk * 32);
    }
    __syncthreads();

    auto load_kv = [&](int c, int stg) {
        const uint32_t base = sb + stg * AT_STAGE;
        const size_t g0 = hoff + (size_t)(c * ST) * HD;
#pragma unroll
        for (int i = 0; i < 2; i++) {
            const int id = tid + 256 * i;
            const int r = id >> 3;
            const int sg = id & 7;
            const uint32_t so = r * KROWB + sg * 16;
            const size_t go = g0 + (size_t)r * HD + sg * 8;
            cpa16(base + so, K16 + go);
            cpa16(base + KVTILE + so, V16 + go);
        }
        CP_COMMIT();
    };

    float m_[2] = {-1e30f, -1e30f};
    float l_[2] = {0.0f, 0.0f};
    float o[8][4];
#pragma unroll
    for (int nf = 0; nf < 8; nf++)
#pragma unroll
        for (int j = 0; j < 4; j++) o[nf][j] = 0.0f;

    const int nch = 2 * qt + 2;
    load_kv(0, 0);
    if (nch > 1) load_kv(1, 1);

    const int rowa = qt * QT + 16 * wid + (lane >> 2);
    const uint32_t xHalf = (lane >> 4) * 16;

    for (int c = 0; c < nch; c++) {
        if (c + 1 < nch) { CP_WAIT(1); } else { CP_WAIT(0); }
        __syncthreads();
        const uint32_t st = sb + (c & 1) * AT_STAGE;

        // ---- S = Q K^T (K fragments via x4 pairs) ----
        float s[8][4];
#pragma unroll
        for (int nf = 0; nf < 8; nf++)
#pragma unroll
            for (int j = 0; j < 4; j++) s[nf][j] = 0.0f;
#pragma unroll
        for (int kk = 0; kk < 4; kk++) {
#pragma unroll
            for (int nfp = 0; nfp < 4; nfp++) {
                uint32_t kq[4];
                ldsm4(kq, st + (nfp * 16 + (lane & 15)) * KROWB + kk * 32 + xHalf);
                uint32_t ke[2] = {kq[0], kq[2]};
                uint32_t ko[2] = {kq[1], kq[3]};
                mma_f16(s[2 * nfp], qa[kk], ke);
                mma_f16(s[2 * nfp + 1], qa[kk], ko);
            }
        }

        // ---- scale + mask ----
        const bool diagc = (c >= 2 * qt);
#pragma unroll
        for (int nf = 0; nf < 8; nf++) {
#pragma unroll
            for (int j = 0; j < 4; j++) {
                float v = s[nf][j] * 0.125f;
                if (diagc) {
                    const int col = c * ST + nf * 8 + 2 * (lane & 3) + (j & 1);
                    const int row = rowa + ((j >> 1) << 3);
                    if (col > row) v = -1e30f;
                }
                s[nf][j] = v;
            }
        }

        // ---- online softmax (warp-local, quad shuffles) ----
        float rma = -1e30f, rmb = -1e30f;
#pragma unroll
        for (int nf = 0; nf < 8; nf++) {
            rma = fmaxf(rma, fmaxf(s[nf][0], s[nf][1]));
            rmb = fmaxf(rmb, fmaxf(s[nf][2], s[nf][3]));
        }
        rma = fmaxf(rma, __shfl_xor_sync(0xffffffffu, rma, 1));
        rma = fmaxf(rma, __shfl_xor_sync(0xffffffffu, rma, 2));
        rmb = fmaxf(rmb, __shfl_xor_sync(0xffffffffu, rmb, 1));
        rmb = fmaxf(rmb, __shfl_xor_sync(0xffffffffu, rmb, 2));

        const float mna = fmaxf(m_[0], rma);
        const float mnb = fmaxf(m_[1], rmb);
        const float ca = __expf(m_[0] - mna);
        const float cb = __expf(m_[1] - mnb);
        float sa = 0.0f, sbv = 0.0f;
#pragma unroll
        for (int nf = 0; nf < 8; nf++) {
            s[nf][0] = __expf(s[nf][0] - mna);
            s[nf][1] = __expf(s[nf][1] - mna);
            s[nf][2] = __expf(s[nf][2] - mnb);
            s[nf][3] = __expf(s[nf][3] - mnb);
            sa += s[nf][0] + s[nf][1];
            sbv += s[nf][2] + s[nf][3];
        }
        sa += __shfl_xor_sync(0xffffffffu, sa, 1);
        sa += __shfl_xor_sync(0xffffffffu, sa, 2);
        sbv += __shfl_xor_sync(0xffffffffu, sbv, 1);
        sbv += __shfl_xor_sync(0xffffffffu, sbv, 2);
        l_[0] = l_[0] * ca + sa;
        l_[1] = l_[1] * cb + sbv;
        m_[0] = mna;
        m_[1] = mnb;
#pragma unroll
        for (int nf = 0; nf < 8; nf++) {
            o[nf][0] *= ca;
            o[nf][1] *= ca;
            o[nf][2] *= cb;
            o[nf][3] *= cb;
        }

        // ---- O += P V (single fp16 P) ----
#pragma unroll
        for (int kk = 0; kk < 4; kk++) {
            uint32_t ph[4];
            __half2 t0 = __floats2half2_rn(s[2 * kk][0], s[2 * kk][1]);
            __half2 t1 = __floats2half2_rn(s[2 * kk][2], s[2 * kk][3]);
            __half2 t2 = __floats2half2_rn(s[2 * kk + 1][0], s[2 * kk + 1][1]);
            __half2 t3 = __floats2half2_rn(s[2 * kk + 1][2], s[2 * kk + 1][3]);
            ph[0] = *(uint32_t*)&t0;
            ph[1] = *(uint32_t*)&t1;
            ph[2] = *(uint32_t*)&t2;
            ph[3] = *(uint32_t*)&t3;
#pragma unroll
            for (int nf = 0; nf < 8; nf++) {
                uint32_t vf[2];
                const uint32_t vo = (kk * 16 + (lane & 15)) * KROWB + nf * 16;
                ldsm2t(vf, st + KVTILE + vo);
                mma_f16(o[nf], ph, vf);
            }
        }
        __syncthreads();
        if (c + 2 < nch) load_kv(c + 2, c & 1);
    }

    // ---- epilogue: normalize, emit fp16 for the w_o GEMM ----
    const int b = bh >> 4;
    const int h = bh & 15;
    const float ia = 1.0f / l_[0];
    const float ib = 1.0f / l_[1];
#pragma unroll
    for (int nf = 0; nf < 8; nf++) {
        const int e = h * 64 + nf * 8 + 2 * (lane & 3);
        __half2 hv = __floats2half2_rn(o[nf][0] * ia, o[nf][1] * ia);
        size_t idx = (size_t)(b * SEQL + rowa) * EMB + e;
        *(uint32_t*)&O16[idx] = *(uint32_t*)&hv;
        hv = __floats2half2_rn(o[nf][2] * ib, o[nf][3] * ib);
        idx = (size_t)(b * SEQL + rowa + 8) * EMB + e;
        *(uint32_t*)&O16[idx] = *(uint32_t*)&hv;
    }
}

// ---------------- launch -----------------------------------------------------
extern "C" void kernel_launch(void* const* d_in, const int* in_sizes, int n_in,
                              void* d_out, int out_size) {
    const float* x = (const float*)d_in[0];
    const float* w_q = (const float*)d_in[1];
    const float* w_k = (const float*)d_in[2];
    const float* w_v = (const float*)d_in[3];
    const float* w_o = (const float*)d_in[4];
    float* out = (float*)d_out;

    __half *x16, *a16, *wq16, *wk16, *wv16, *wo16, *q16, *k16, *v16;
    cudaGetSymbolAddress((void**)&x16, g_x16);
    cudaGetSymbolAddress((void**)&a16, g_a16);
    cudaGetSymbolAddress((void**)&wq16, g_wq16);
    cudaGetSymbolAddress((void**)&wk16, g_wk16);
    cudaGetSymbolAddress((void**)&wv16, g_wv16);
    cudaGetSymbolAddress((void**)&wo16, g_wo16);
    cudaGetSymbolAddress((void**)&q16, g_q16);
    cudaGetSymbolAddress((void**)&k16, g_k16);
    cudaGetSymbolAddress((void**)&v16, g_v16);

    cudaFuncSetAttribute(gemm_mma<0>, cudaFuncAttributeMaxDynamicSharedMemorySize, SM_TOTAL);
    cudaFuncSetAttribute(gemm_mma<1>, cudaFuncAttributeMaxDynamicSharedMemorySize, SM_TOTAL);
    cudaFuncSetAttribute(attn_mma, cudaFuncAttributeMaxDynamicSharedMemorySize, AT_SMEM);

    cvt_all<<<4096 + 4 * 1024, 256>>>(x, w_q, w_k, w_v, w_o,
                                      x16, wq16, wk16, wv16, wo16);

    dim3 ggrid(EMB / TN, MROWS / TM);  // (8, 32)
    gemm_mma<1><<<ggrid, 256, SM_TOTAL>>>(x16, wq16, nullptr, q16);
    gemm_mma<1><<<ggrid, 256, SM_TOTAL>>>(x16, wk16, nullptr, k16);
    gemm_mma<1><<<ggrid, 256, SM_TOTAL>>>(x16, wv16, nullptr, v16);

    attn_mma<<<(SEQL / QT) * BSZ * NH, 256, AT_SMEM>>>(q16, k16, v16, a16);

    gemm_mma<0><<<ggrid, 256, SM_TOTAL>>>(a16, wo16, out, nullptr);
}

// round 13
// speedup vs baseline: 3.7166x; 1.0324x over previous
#include <cuda_runtime.h>
#include <cuda_fp16.h>
#include <cstdint>

#define BSZ 2
#define SEQL 2048
#define EMB 1024
#define NH 16
#define HD 64
#define MROWS (BSZ * SEQL)

// ---------------- scratch (__device__ globals; no allocs allowed) ----------
__device__ __half g_x16[MROWS * EMB];
__device__ __half g_a16[MROWS * EMB];
__device__ __half g_wq16[EMB * EMB], g_wk16[EMB * EMB];
__device__ __half g_wv16[EMB * EMB], g_wo16[EMB * EMB];
__device__ __half g_q16[BSZ * NH * SEQL * HD];
__device__ __half g_k16[BSZ * NH * SEQL * HD];
__device__ __half g_v16[BSZ * NH * SEQL * HD];

// ---------------- PTX helpers (family-compatible, sm_80-era) ----------------
__device__ __forceinline__ uint32_t s2u(const void* p) {
    uint32_t a;
    asm("{ .reg .u64 t; cvta.to.shared.u64 t, %1; cvt.u32.u64 %0, t; }"
        : "=r"(a) : "l"(p));
    return a;
}
__device__ __forceinline__ void cpa16(uint32_t d, const void* g) {
    asm volatile("cp.async.cg.shared.global [%0], [%1], 16;" :: "r"(d), "l"(g));
}
#define CP_COMMIT() asm volatile("cp.async.commit_group;" ::: "memory")
#define CP_WAIT(n) asm volatile("cp.async.wait_group %0;" :: "n"(n) : "memory")

__device__ __forceinline__ void ldsm4(uint32_t* r, uint32_t a) {
    asm volatile("ldmatrix.sync.aligned.m8n8.x4.shared.b16 {%0,%1,%2,%3}, [%4];"
                 : "=r"(r[0]), "=r"(r[1]), "=r"(r[2]), "=r"(r[3]) : "r"(a));
}
__device__ __forceinline__ void ldsm2t(uint32_t* r, uint32_t a) {
    asm volatile("ldmatrix.sync.aligned.m8n8.x2.trans.shared.b16 {%0,%1}, [%2];"
                 : "=r"(r[0]), "=r"(r[1]) : "r"(a));
}
__device__ __forceinline__ void mma_f16(float* c, const uint32_t* a, const uint32_t* b) {
    asm volatile(
        "mma.sync.aligned.m16n8k16.row.col.f32.f16.f16.f32 "
        "{%0,%1,%2,%3}, {%4,%5,%6,%7}, {%8,%9}, {%0,%1,%2,%3};"
        : "+f"(c[0]), "+f"(c[1]), "+f"(c[2]), "+f"(c[3])
        : "r"(a[0]), "r"(a[1]), "r"(a[2]), "r"(a[3]), "r"(b[0]), "r"(b[1]));
}

// ---------------- all fp32 -> fp16 conversions in ONE kernel ----------------
__global__ __launch_bounds__(256) void cvt_all(
    const float* __restrict__ x, const float* __restrict__ wq,
    const float* __restrict__ wk, const float* __restrict__ wv,
    const float* __restrict__ wo,
    __half* __restrict__ x16, __half* __restrict__ wq16,
    __half* __restrict__ wk16, __half* __restrict__ wv16,
    __half* __restrict__ wo16) {
    const int b = blockIdx.x;
    const float* in;
    __half* out;
    int i;
    if (b < 4096) {
        in = x; out = x16; i = b * 256 + threadIdx.x;
    } else {
        const int w = (b - 4096) >> 10;
        i = ((b - 4096) & 1023) * 256 + threadIdx.x;
        in = (w == 0) ? wq : (w == 1) ? wk : (w == 2) ? wv : wo;
        out = (w == 0) ? wq16 : (w == 1) ? wk16 : (w == 2) ? wv16 : wo16;
    }
    float4 v = ((const float4*)in)[i];
    __half2 a = __floats2half2_rn(v.x, v.y);
    __half2 c = __floats2half2_rn(v.z, v.w);
    ((uint32_t*)out)[2 * i] = *(uint32_t*)&a;
    ((uint32_t*)out)[2 * i + 1] = *(uint32_t*)&c;
}

// ---------------- fp16 GEMM common config -----------------------------------
#define TM 128
#define TN 128
#define KB 64
#define NCH (EMB / KB)               // 16
#define ROWB 144
#define MAT_B (128 * ROWB)           // 18432
#define OFF_A 0
#define OFF_B MAT_B
#define STAGE_B (2 * MAT_B)          // 36864
#define SM_TOTAL (2 * STAGE_B)       // 73728

// Fragment loads for one k16 step: 2 A-ldsm4 + 4 B-ldsm4.
#define LOAD_FRAGS(st, kk, ah, bq)                                              \
    do {                                                                        \
        _Pragma("unroll") for (int mf = 0; mf < 2; mf++)                        \
            ldsm4((ah)[mf],                                                     \
                  (st) + OFF_A + (aRow + mf * 16) * ROWB + (kk) * 32 + xHalf);  \
        _Pragma("unroll") for (int nfp = 0; nfp < 4; nfp++)                     \
            ldsm4((bq)[nfp],                                                    \
                  (st) + OFF_B + (bRow + nfp * 16) * ROWB + (kk) * 32 + xHalf); \
    } while (0)

#define DO_MMAS(ah, bq, acc)                                                    \
    do {                                                                        \
        _Pragma("unroll") for (int nfp = 0; nfp < 4; nfp++) {                   \
            uint32_t be[2] = {(bq)[nfp][0], (bq)[nfp][2]};                      \
            uint32_t bo[2] = {(bq)[nfp][1], (bq)[nfp][3]};                      \
            _Pragma("unroll") for (int mf = 0; mf < 2; mf++) {                  \
                mma_f16((acc)[mf][2 * nfp], (ah)[mf], be);                      \
                mma_f16((acc)[mf][2 * nfp + 1], (ah)[mf], bo);                  \
            }                                                                   \
        }                                                                       \
    } while (0)

// ---------------- fused QKV GEMM: {Q,K,V} = x @ W^T, scatter [b,h,s,d] -------
__global__ __launch_bounds__(256, 2)
void gemm_qkv(const __half* __restrict__ A16,
              const __half* __restrict__ Wq, const __half* __restrict__ Wk,
              const __half* __restrict__ Wv,
              __half* __restrict__ Qo, __half* __restrict__ Ko,
              __half* __restrict__ Vo) {
    extern __shared__ __align__(128) char smem[];
    const uint32_t sb = s2u(smem);
    const int tid = threadIdx.x;
    const int wid = tid >> 5;
    const int lane = tid & 31;
    const int w = blockIdx.x >> 3;
    const int n0 = (blockIdx.x & 7) * TN;
    const int m0 = blockIdx.y * TM;
    const __half* B16 = (w == 0) ? Wq : (w == 1) ? Wk : Wv;
    __half* Ch = (w == 0) ? Qo : (w == 1) ? Ko : Vo;
    const int wm0 = (wid >> 1) * 32;
    const int wn0 = (wid & 1) * 64;

    const int lr = tid >> 1;
    const int lc = (tid & 1) * 4;
    const __half* pA = A16 + (size_t)(m0 + lr) * EMB + lc * 8;
    const __half* pB = B16 + (size_t)(n0 + lr) * EMB + lc * 8;
    const uint32_t so0 = lr * ROWB + lc * 16;

    auto load_chunk = [&](int c, int s) {
        const uint32_t base = sb + s * STAGE_B;
        const int kb = c * KB;
#pragma unroll
        for (int i = 0; i < 4; i++) {
            cpa16(base + OFF_A + so0 + i * 16, pA + kb + i * 8);
            cpa16(base + OFF_B + so0 + i * 16, pB + kb + i * 8);
        }
        CP_COMMIT();
    };

    float acc[2][8][4];
#pragma unroll
    for (int mf = 0; mf < 2; mf++)
#pragma unroll
        for (int nf = 0; nf < 8; nf++)
#pragma unroll
            for (int j = 0; j < 4; j++) acc[mf][nf][j] = 0.0f;

    const uint32_t aRow = wm0 + (lane & 15);
    const uint32_t xHalf = (lane >> 4) * 16;
    const uint32_t bRow = wn0 + (lane & 15);

    load_chunk(0, 0);

    for (int c = 0; c < NCH; c++) {
        CP_WAIT(0);
        __syncthreads();
        if (c + 1 < NCH) load_chunk(c + 1, (c + 1) & 1);

        const uint32_t st = sb + (c & 1) * STAGE_B;
        uint32_t ah[2][2][4], bq[2][4][4];
        LOAD_FRAGS(st, 0, ah[0], bq[0]);
#pragma unroll
        for (int kk = 0; kk < 4; kk++) {
            const int cur = kk & 1;
            if (kk < 3) LOAD_FRAGS(st, kk + 1, ah[cur ^ 1], bq[cur ^ 1]);
            DO_MMAS(ah[cur], bq[cur], acc);
        }
    }

#pragma unroll
    for (int mf = 0; mf < 2; mf++) {
        const int mrow = m0 + wm0 + mf * 16 + (lane >> 2);
#pragma unroll
        for (int half = 0; half < 2; half++) {
            const int row = mrow + half * 8;
            const int b = row >> 11;
            const int sdx = row & (SEQL - 1);
#pragma unroll
            for (int nf = 0; nf < 8; nf++) {
                const int col = n0 + wn0 + nf * 8 + 2 * (lane & 3);
                const int h = col >> 6;
                const int d = col & 63;
                const size_t idx = (((size_t)(b * NH + h) * SEQL + sdx) << 6) + d;
                __half2 hv2 = __floats2half2_rn(acc[mf][nf][2 * half],
                                                acc[mf][nf][2 * half + 1]);
                *(uint32_t*)&Ch[idx] = *(uint32_t*)&hv2;
            }
        }
    }
}

// ---------------- output-projection GEMM: out = attn @ Wo^T (fp32 out) ------
__global__ __launch_bounds__(256, 2)
void gemm_out(const __half* __restrict__ A16, const __half* __restrict__ B16,
              float* __restrict__ C) {
    extern __shared__ __align__(128) char smem[];
    const uint32_t sb = s2u(smem);
    const int tid = threadIdx.x;
    const int wid = tid >> 5;
    const int lane = tid & 31;
    const int m0 = blockIdx.y * TM;
    const int n0 = blockIdx.x * TN;
    const int wm0 = (wid >> 1) * 32;
    const int wn0 = (wid & 1) * 64;

    const int lr = tid >> 1;
    const int lc = (tid & 1) * 4;
    const __half* pA = A16 + (size_t)(m0 + lr) * EMB + lc * 8;
    const __half* pB = B16 + (size_t)(n0 + lr) * EMB + lc * 8;
    const uint32_t so0 = lr * ROWB + lc * 16;

    auto load_chunk = [&](int c, int s) {
        const uint32_t base = sb + s * STAGE_B;
        const int kb = c * KB;
#pragma unroll
        for (int i = 0; i < 4; i++) {
            cpa16(base + OFF_A + so0 + i * 16, pA + kb + i * 8);
            cpa16(base + OFF_B + so0 + i * 16, pB + kb + i * 8);
        }
        CP_COMMIT();
    };

    float acc[2][8][4];
#pragma unroll
    for (int mf = 0; mf < 2; mf++)
#pragma unroll
        for (int nf = 0; nf < 8; nf++)
#pragma unroll
            for (int j = 0; j < 4; j++) acc[mf][nf][j] = 0.0f;

    const uint32_t aRow = wm0 + (lane & 15);
    const uint32_t xHalf = (lane >> 4) * 16;
    const uint32_t bRow = wn0 + (lane & 15);

    load_chunk(0, 0);

    for (int c = 0; c < NCH; c++) {
        CP_WAIT(0);
        __syncthreads();
        if (c + 1 < NCH) load_chunk(c + 1, (c + 1) & 1);

        const uint32_t st = sb + (c & 1) * STAGE_B;
        uint32_t ah[2][2][4], bq[2][4][4];
        LOAD_FRAGS(st, 0, ah[0], bq[0]);
#pragma unroll
        for (int kk = 0; kk < 4; kk++) {
            const int cur = kk & 1;
            if (kk < 3) LOAD_FRAGS(st, kk + 1, ah[cur ^ 1], bq[cur ^ 1]);
            DO_MMAS(ah[cur], bq[cur], acc);
        }
    }

#pragma unroll
    for (int mf = 0; mf < 2; mf++) {
        const int mrow = m0 + wm0 + mf * 16 + (lane >> 2);
#pragma unroll
        for (int half = 0; half < 2; half++) {
            const int row = mrow + half * 8;
#pragma unroll
            for (int nf = 0; nf < 8; nf++) {
                const int col = n0 + wn0 + nf * 8 + 2 * (lane & 3);
                float2 v = {acc[mf][nf][2 * half], acc[mf][nf][2 * half + 1]};
                *(float2*)&C[(size_t)row * EMB + col] = v;
            }
        }
    }
}

// ---------------- tensor-core causal flash attention (single fp16) ----------
#define QT 128
#define ST 64
#define KROWB 144
#define KVTILE (ST * KROWB)          // 9216
#define AT_STAGE (2 * KVTILE)        // 18432
#define AT_SMEM (2 * AT_STAGE)       // 36864
#define QSTG (QT * KROWB)            // 18432

__global__ __launch_bounds__(256, 1)
void attn_mma(const __half* __restrict__ Q16, const __half* __restrict__ K16,
              const __half* __restrict__ V16, __half* __restrict__ O16) {
    extern __shared__ __align__(128) char smem[];
    const uint32_t sb = s2u(smem);
    const int tid = threadIdx.x;
    const int wid = tid >> 5;
    const int lane = tid & 31;
    const int qt = (SEQL / QT - 1) - (blockIdx.x >> 5);  // heavy tiles first
    const int bh = blockIdx.x & 31;
    const size_t hoff = (size_t)bh * SEQL * HD;

    {
        const int r = tid >> 1;
        const int cs = (tid & 1) * 4;
        const __half* qp = Q16 + hoff + (size_t)(qt * QT + r) * HD + cs * 8;
#pragma unroll
        for (int i = 0; i < 4; i++)
            cpa16(sb + r * KROWB + (cs + i) * 16, qp + i * 8);
        CP_COMMIT();
        CP_WAIT(0);
        __syncthreads();
    }
    uint32_t qa[4][4];
    {
        const uint32_t qa0 = (16 * wid + (lane & 15)) * KROWB + (lane >> 4) * 16;
#pragma unroll
        for (int kk = 0; kk < 4; kk++) ldsm4(qa[kk], sb + qa0 + kk * 32);
    }
    __syncthreads();

    auto load_kv = [&](int c, int stg) {
        const uint32_t base = sb + stg * AT_STAGE;
        const size_t g0 = hoff + (size_t)(c * ST) * HD;
#pragma unroll
        for (int i = 0; i < 2; i++) {
            const int id = tid + 256 * i;
            const int r = id >> 3;
            const int sg = id & 7;
            const uint32_t so = r * KROWB + sg * 16;
            const size_t go = g0 + (size_t)r * HD + sg * 8;
            cpa16(base + so, K16 + go);
            cpa16(base + KVTILE + so, V16 + go);
        }
        CP_COMMIT();
    };

    float m_[2] = {-1e30f, -1e30f};
    float l_[2] = {0.0f, 0.0f};
    float o[8][4];
#pragma unroll
    for (int nf = 0; nf < 8; nf++)
#pragma unroll
        for (int j = 0; j < 4; j++) o[nf][j] = 0.0f;

    const int nch = 2 * qt + 2;
    load_kv(0, 0);
    if (nch > 1) load_kv(1, 1);

    const int rowa = qt * QT + 16 * wid + (lane >> 2);
    const uint32_t xHalf = (lane >> 4) * 16;

    for (int c = 0; c < nch; c++) {
        if (c + 1 < nch) { CP_WAIT(1); } else { CP_WAIT(0); }
        __syncthreads();
        const uint32_t st = sb + (c & 1) * AT_STAGE;

        float s[8][4];
#pragma unroll
        for (int nf = 0; nf < 8; nf++)
#pragma unroll
            for (int j = 0; j < 4; j++) s[nf][j] = 0.0f;
#pragma unroll
        for (int kk = 0; kk < 4; kk++) {
#pragma unroll
            for (int nfp = 0; nfp < 4; nfp++) {
                uint32_t kq[4];
                ldsm4(kq, st + (nfp * 16 + (lane & 15)) * KROWB + kk * 32 + xHalf);
                uint32_t ke[2] = {kq[0], kq[2]};
                uint32_t ko[2] = {kq[1], kq[3]};
                mma_f16(s[2 * nfp], qa[kk], ke);
                mma_f16(s[2 * nfp + 1], qa[kk], ko);
            }
        }

        const bool diagc = (c >= 2 * qt);
#pragma unroll
        for (int nf = 0; nf < 8; nf++) {
#pragma unroll
            for (int j = 0; j < 4; j++) {
                float v = s[nf][j] * 0.125f;
                if (diagc) {
                    const int col = c * ST + nf * 8 + 2 * (lane & 3) + (j & 1);
                    const int row = rowa + ((j >> 1) << 3);
                    if (col > row) v = -1e30f;
                }
                s[nf][j] = v;
            }
        }

        float rma = -1e30f, rmb = -1e30f;
#pragma unroll
        for (int nf = 0; nf < 8; nf++) {
            rma = fmaxf(rma, fmaxf(s[nf][0], s[nf][1]));
            rmb = fmaxf(rmb, fmaxf(s[nf][2], s[nf][3]));
        }
        rma = fmaxf(rma, __shfl_xor_sync(0xffffffffu, rma, 1));
        rma = fmaxf(rma, __shfl_xor_sync(0xffffffffu, rma, 2));
        rmb = fmaxf(rmb, __shfl_xor_sync(0xffffffffu, rmb, 1));
        rmb = fmaxf(rmb, __shfl_xor_sync(0xffffffffu, rmb, 2));

        const float mna = fmaxf(m_[0], rma);
        const float mnb = fmaxf(m_[1], rmb);
        const float ca = __expf(m_[0] - mna);
        const float cb = __expf(m_[1] - mnb);
        float sa = 0.0f, sbv = 0.0f;
#pragma unroll
        for (int nf = 0; nf < 8; nf++) {
            s[nf][0] = __expf(s[nf][0] - mna);
            s[nf][1] = __expf(s[nf][1] - mna);
            s[nf][2] = __expf(s[nf][2] - mnb);
            s[nf][3] = __expf(s[nf][3] - mnb);
            sa += s[nf][0] + s[nf][1];
            sbv += s[nf][2] + s[nf][3];
        }
        sa += __shfl_xor_sync(0xffffffffu, sa, 1);
        sa += __shfl_xor_sync(0xffffffffu, sa, 2);
        sbv += __shfl_xor_sync(0xffffffffu, sbv, 1);
        sbv += __shfl_xor_sync(0xffffffffu, sbv, 2);
        l_[0] = l_[0] * ca + sa;
        l_[1] = l_[1] * cb + sbv;
        m_[0] = mna;
        m_[1] = mnb;
#pragma unroll
        for (int nf = 0; nf < 8; nf++) {
            o[nf][0] *= ca;
            o[nf][1] *= ca;
            o[nf][2] *= cb;
            o[nf][3] *= cb;
        }

#pragma unroll
        for (int kk = 0; kk < 4; kk++) {
            uint32_t ph[4];
            __half2 t0 = __floats2half2_rn(s[2 * kk][0], s[2 * kk][1]);
            __half2 t1 = __floats2half2_rn(s[2 * kk][2], s[2 * kk][3]);
            __half2 t2 = __floats2half2_rn(s[2 * kk + 1][0], s[2 * kk + 1][1]);
            __half2 t3 = __floats2half2_rn(s[2 * kk + 1][2], s[2 * kk + 1][3]);
            ph[0] = *(uint32_t*)&t0;
            ph[1] = *(uint32_t*)&t1;
            ph[2] = *(uint32_t*)&t2;
            ph[3] = *(uint32_t*)&t3;
#pragma unroll
            for (int nf = 0; nf < 8; nf++) {
                uint32_t vf[2];
                const uint32_t vo = (kk * 16 + (lane & 15)) * KROWB + nf * 16;
                ldsm2t(vf, st + KVTILE + vo);
                mma_f16(o[nf], ph, vf);
            }
        }
        __syncthreads();
        if (c + 2 < nch) load_kv(c + 2, c & 1);
    }

    const int b = bh >> 4;
    const int h = bh & 15;
    const float ia = 1.0f / l_[0];
    const float ib = 1.0f / l_[1];
#pragma unroll
    for (int nf = 0; nf < 8; nf++) {
        const int e = h * 64 + nf * 8 + 2 * (lane & 3);
        __half2 hv = __floats2half2_rn(o[nf][0] * ia, o[nf][1] * ia);
        size_t idx = (size_t)(b * SEQL + rowa) * EMB + e;
        *(uint32_t*)&O16[idx] = *(uint32_t*)&hv;
        hv = __floats2half2_rn(o[nf][2] * ib, o[nf][3] * ib);
        idx = (size_t)(b * SEQL + rowa + 8) * EMB + e;
        *(uint32_t*)&O16[idx] = *(uint32_t*)&hv;
    }
}

// ---------------- launch -----------------------------------------------------
extern "C" void kernel_launch(void* const* d_in, const int* in_sizes, int n_in,
                              void* d_out, int out_size) {
    const float* x = (const float*)d_in[0];
    const float* w_q = (const float*)d_in[1];
    const float* w_k = (const float*)d_in[2];
    const float* w_v = (const float*)d_in[3];
    const float* w_o = (const float*)d_in[4];
    float* out = (float*)d_out;

    __half *x16, *a16, *wq16, *wk16, *wv16, *wo16, *q16, *k16, *v16;
    cudaGetSymbolAddress((void**)&x16, g_x16);
    cudaGetSymbolAddress((void**)&a16, g_a16);
    cudaGetSymbolAddress((void**)&wq16, g_wq16);
    cudaGetSymbolAddress((void**)&wk16, g_wk16);
    cudaGetSymbolAddress((void**)&wv16, g_wv16);
    cudaGetSymbolAddress((void**)&wo16, g_wo16);
    cudaGetSymbolAddress((void**)&q16, g_q16);
    cudaGetSymbolAddress((void**)&k16, g_k16);
    cudaGetSymbolAddress((void**)&v16, g_v16);

    cudaFuncSetAttribute(gemm_qkv, cudaFuncAttributeMaxDynamicSharedMemorySize, SM_TOTAL);
    cudaFuncSetAttribute(gemm_out, cudaFuncAttributeMaxDynamicSharedMemorySize, SM_TOTAL);
    cudaFuncSetAttribute(attn_mma, cudaFuncAttributeMaxDynamicSharedMemorySize, AT_SMEM);

    cvt_all<<<4096 + 4 * 1024, 256>>>(x, w_q, w_k, w_v, w_o,
                                      x16, wq16, wk16, wv16, wo16);

    dim3 qkvgrid(24, 32);  // x: 3 weights x 8 n-tiles; y: 32 m-tiles
    gemm_qkv<<<qkvgrid, 256, SM_TOTAL>>>(x16, wq16, wk16, wv16, q16, k16, v16);

    attn_mma<<<(SEQL / QT) * BSZ * NH, 256, AT_SMEM>>>(q16, k16, v16, a16);

    dim3 ogrid(8, 32);
    gemm_out<<<ogrid, 256, SM_TOTAL>>>(a16, wo16, out);
}

// round 14
// speedup vs baseline: 3.9655x; 1.0670x over previous
#include <cuda_runtime.h>
#include <cuda_fp16.h>
#include <cstdint>

#define BSZ 2
#define SEQL 2048
#define EMB 1024
#define NH 16
#define HD 64
#define MROWS (BSZ * SEQL)

// ---------------- scratch (__device__ globals; no allocs allowed) ----------
__device__ __half g_x16[MROWS * EMB];
__device__ __half g_a16[MROWS * EMB];
__device__ __half g_wq16[EMB * EMB], g_wk16[EMB * EMB];
__device__ __half g_wv16[EMB * EMB], g_wo16[EMB * EMB];
__device__ __half g_q16[BSZ * NH * SEQL * HD];
__device__ __half g_k16[BSZ * NH * SEQL * HD];
__device__ __half g_v16[BSZ * NH * SEQL * HD];

// ---------------- PTX helpers (family-compatible, sm_80-era) ----------------
__device__ __forceinline__ uint32_t s2u(const void* p) {
    uint32_t a;
    asm("{ .reg .u64 t; cvta.to.shared.u64 t, %1; cvt.u32.u64 %0, t; }"
        : "=r"(a) : "l"(p));
    return a;
}
__device__ __forceinline__ void cpa16(uint32_t d, const void* g) {
    asm volatile("cp.async.cg.shared.global [%0], [%1], 16;" :: "r"(d), "l"(g));
}
#define CP_COMMIT() asm volatile("cp.async.commit_group;" ::: "memory")
#define CP_WAIT(n) asm volatile("cp.async.wait_group %0;" :: "n"(n) : "memory")

__device__ __forceinline__ void ldsm4(uint32_t* r, uint32_t a) {
    asm volatile("ldmatrix.sync.aligned.m8n8.x4.shared.b16 {%0,%1,%2,%3}, [%4];"
                 : "=r"(r[0]), "=r"(r[1]), "=r"(r[2]), "=r"(r[3]) : "r"(a));
}
__device__ __forceinline__ void ldsm2t(uint32_t* r, uint32_t a) {
    asm volatile("ldmatrix.sync.aligned.m8n8.x2.trans.shared.b16 {%0,%1}, [%2];"
                 : "=r"(r[0]), "=r"(r[1]) : "r"(a));
}
__device__ __forceinline__ void mma_f16(float* c, const uint32_t* a, const uint32_t* b) {
    asm volatile(
        "mma.sync.aligned.m16n8k16.row.col.f32.f16.f16.f32 "
        "{%0,%1,%2,%3}, {%4,%5,%6,%7}, {%8,%9}, {%0,%1,%2,%3};"
        : "+f"(c[0]), "+f"(c[1]), "+f"(c[2]), "+f"(c[3])
        : "r"(a[0]), "r"(a[1]), "r"(a[2]), "r"(a[3]), "r"(b[0]), "r"(b[1]));
}

// ---------------- all fp32 -> fp16 conversions in ONE kernel ----------------
__global__ __launch_bounds__(256) void cvt_all(
    const float* __restrict__ x, const float* __restrict__ wq,
    const float* __restrict__ wk, const float* __restrict__ wv,
    const float* __restrict__ wo,
    __half* __restrict__ x16, __half* __restrict__ wq16,
    __half* __restrict__ wk16, __half* __restrict__ wv16,
    __half* __restrict__ wo16) {
    const int b = blockIdx.x;
    const float* in;
    __half* out;
    int i;
    if (b < 4096) {
        in = x; out = x16; i = b * 256 + threadIdx.x;
    } else {
        const int w = (b - 4096) >> 10;
        i = ((b - 4096) & 1023) * 256 + threadIdx.x;
        in = (w == 0) ? wq : (w == 1) ? wk : (w == 2) ? wv : wo;
        out = (w == 0) ? wq16 : (w == 1) ? wk16 : (w == 2) ? wv16 : wo16;
    }
    float4 v = ((const float4*)in)[i];
    __half2 a = __floats2half2_rn(v.x, v.y);
    __half2 c = __floats2half2_rn(v.z, v.w);
    ((uint32_t*)out)[2 * i] = *(uint32_t*)&a;
    ((uint32_t*)out)[2 * i + 1] = *(uint32_t*)&c;
}

// ---------------- fp16 GEMM common config -----------------------------------
// CTA tile 128x128, BK=32, 4-stage cp.async ring, prefetch distance 3.
#define TM 128
#define TN 128
#define KB 32
#define NCH (EMB / KB)               // 32
#define ROWB 80                      // 32 halfs = 64B data + 16B pad
#define MAT_B (128 * ROWB)           // 10240
#define OFF_A 0
#define OFF_B MAT_B
#define STAGE_B (2 * MAT_B)          // 20480
#define NSTG 4
#define SM_TOTAL (NSTG * STAGE_B)    // 81920

// Fragment loads for one k16 step: 2 A-ldsm4 + 4 B-ldsm4.
#define LOAD_FRAGS(st, kk, ah, bq)                                              \
    do {                                                                        \
        _Pragma("unroll") for (int mf = 0; mf < 2; mf++)                        \
            ldsm4((ah)[mf],                                                     \
                  (st) + OFF_A + (aRow + mf * 16) * ROWB + (kk) * 32 + xHalf);  \
        _Pragma("unroll") for (int nfp = 0; nfp < 4; nfp++)                     \
            ldsm4((bq)[nfp],                                                    \
                  (st) + OFF_B + (bRow + nfp * 16) * ROWB + (kk) * 32 + xHalf); \
    } while (0)

#define DO_MMAS(ah, bq, acc)                                                    \
    do {                                                                        \
        _Pragma("unroll") for (int nfp = 0; nfp < 4; nfp++) {                   \
            uint32_t be[2] = {(bq)[nfp][0], (bq)[nfp][2]};                      \
            uint32_t bo[2] = {(bq)[nfp][1], (bq)[nfp][3]};                      \
            _Pragma("unroll") for (int mf = 0; mf < 2; mf++) {                  \
                mma_f16((acc)[mf][2 * nfp], (ah)[mf], be);                      \
                mma_f16((acc)[mf][2 * nfp + 1], (ah)[mf], bo);                  \
            }                                                                   \
        }                                                                       \
    } while (0)

// Shared mainloop body (4-stage ring): declared as a macro so both kernels use it.
#define GEMM_MAINLOOP(load_chunk)                                               \
    load_chunk(0, 0);                                                           \
    load_chunk(1, 1);                                                           \
    load_chunk(2, 2);                                                           \
    for (int c = 0; c < NCH; c++) {                                             \
        if (c <= NCH - 3) { CP_WAIT(2); }                                       \
        else if (c == NCH - 2) { CP_WAIT(1); }                                  \
        else { CP_WAIT(0); }                                                    \
        __syncthreads();                                                        \
        if (c + 3 < NCH) load_chunk(c + 3, (c + 3) & 3);                        \
        const uint32_t st = sb + (c & 3) * STAGE_B;                             \
        _Pragma("unroll") for (int kk = 0; kk < 2; kk++) {                      \
            uint32_t ah[2][4], bq[4][4];                                        \
            LOAD_FRAGS(st, kk, ah, bq);                                         \
            DO_MMAS(ah, bq, acc);                                               \
        }                                                                       \
    }

// ---------------- fused QKV GEMM: {Q,K,V} = x @ W^T, scatter [b,h,s,d] -------
__global__ __launch_bounds__(256, 2)
void gemm_qkv(const __half* __restrict__ A16,
              const __half* __restrict__ Wq, const __half* __restrict__ Wk,
              const __half* __restrict__ Wv,
              __half* __restrict__ Qo, __half* __restrict__ Ko,
              __half* __restrict__ Vo) {
    extern __shared__ __align__(128) char smem[];
    const uint32_t sb = s2u(smem);
    const int tid = threadIdx.x;
    const int wid = tid >> 5;
    const int lane = tid & 31;
    const int w = blockIdx.x >> 3;
    const int n0 = (blockIdx.x & 7) * TN;
    const int m0 = blockIdx.y * TM;
    const __half* B16 = (w == 0) ? Wq : (w == 1) ? Wk : Wv;
    __half* Ch = (w == 0) ? Qo : (w == 1) ? Ko : Vo;
    const int wm0 = (wid >> 1) * 32;
    const int wn0 = (wid & 1) * 64;

    // load geometry: row = tid>>1 (0..127), 2 x 16B chunks at (tid&1)*2
    const int lr = tid >> 1;
    const int lcw = (tid & 1) * 2;
    const __half* pA = A16 + (size_t)(m0 + lr) * EMB + lcw * 8;
    const __half* pB = B16 + (size_t)(n0 + lr) * EMB + lcw * 8;
    const uint32_t so0 = lr * ROWB + lcw * 16;

    auto load_chunk = [&](int c, int s) {
        const uint32_t base = sb + s * STAGE_B;
        const int kb = c * KB;
        cpa16(base + OFF_A + so0, pA + kb);
        cpa16(base + OFF_A + so0 + 16, pA + kb + 8);
        cpa16(base + OFF_B + so0, pB + kb);
        cpa16(base + OFF_B + so0 + 16, pB + kb + 8);
        CP_COMMIT();
    };

    float acc[2][8][4];
#pragma unroll
    for (int mf = 0; mf < 2; mf++)
#pragma unroll
        for (int nf = 0; nf < 8; nf++)
#pragma unroll
            for (int j = 0; j < 4; j++) acc[mf][nf][j] = 0.0f;

    const uint32_t aRow = wm0 + (lane & 15);
    const uint32_t xHalf = (lane >> 4) * 16;
    const uint32_t bRow = wn0 + (lane & 15);

    GEMM_MAINLOOP(load_chunk)

#pragma unroll
    for (int mf = 0; mf < 2; mf++) {
        const int mrow = m0 + wm0 + mf * 16 + (lane >> 2);
#pragma unroll
        for (int half = 0; half < 2; half++) {
            const int row = mrow + half * 8;
            const int b = row >> 11;
            const int sdx = row & (SEQL - 1);
#pragma unroll
            for (int nf = 0; nf < 8; nf++) {
                const int col = n0 + wn0 + nf * 8 + 2 * (lane & 3);
                const int h = col >> 6;
                const int d = col & 63;
                const size_t idx = (((size_t)(b * NH + h) * SEQL + sdx) << 6) + d;
                __half2 hv2 = __floats2half2_rn(acc[mf][nf][2 * half],
                                                acc[mf][nf][2 * half + 1]);
                *(uint32_t*)&Ch[idx] = *(uint32_t*)&hv2;
            }
        }
    }
}

// ---------------- output-projection GEMM: out = attn @ Wo^T (fp32 out) ------
__global__ __launch_bounds__(256, 2)
void gemm_out(const __half* __restrict__ A16, const __half* __restrict__ B16,
              float* __restrict__ C) {
    extern __shared__ __align__(128) char smem[];
    const uint32_t sb = s2u(smem);
    const int tid = threadIdx.x;
    const int wid = tid >> 5;
    const int lane = tid & 31;
    const int m0 = blockIdx.y * TM;
    const int n0 = blockIdx.x * TN;
    const int wm0 = (wid >> 1) * 32;
    const int wn0 = (wid & 1) * 64;

    const int lr = tid >> 1;
    const int lcw = (tid & 1) * 2;
    const __half* pA = A16 + (size_t)(m0 + lr) * EMB + lcw * 8;
    const __half* pB = B16 + (size_t)(n0 + lr) * EMB + lcw * 8;
    const uint32_t so0 = lr * ROWB + lcw * 16;

    auto load_chunk = [&](int c, int s) {
        const uint32_t base = sb + s * STAGE_B;
        const int kb = c * KB;
        cpa16(base + OFF_A + so0, pA + kb);
        cpa16(base + OFF_A + so0 + 16, pA + kb + 8);
        cpa16(base + OFF_B + so0, pB + kb);
        cpa16(base + OFF_B + so0 + 16, pB + kb + 8);
        CP_COMMIT();
    };

    float acc[2][8][4];
#pragma unroll
    for (int mf = 0; mf < 2; mf++)
#pragma unroll
        for (int nf = 0; nf < 8; nf++)
#pragma unroll
            for (int j = 0; j < 4; j++) acc[mf][nf][j] = 0.0f;

    const uint32_t aRow = wm0 + (lane & 15);
    const uint32_t xHalf = (lane >> 4) * 16;
    const uint32_t bRow = wn0 + (lane & 15);

    GEMM_MAINLOOP(load_chunk)

#pragma unroll
    for (int mf = 0; mf < 2; mf++) {
        const int mrow = m0 + wm0 + mf * 16 + (lane >> 2);
#pragma unroll
        for (int half = 0; half < 2; half++) {
            const int row = mrow + half * 8;
#pragma unroll
            for (int nf = 0; nf < 8; nf++) {
                const int col = n0 + wn0 + nf * 8 + 2 * (lane & 3);
                float2 v = {acc[mf][nf][2 * half], acc[mf][nf][2 * half + 1]};
                *(float2*)&C[(size_t)row * EMB + col] = v;
            }
        }
    }
}

// ---------------- tensor-core causal flash attention (single fp16) ----------
#define QT 128
#define ST 64
#define KROWB 144
#define KVTILE (ST * KROWB)          // 9216
#define AT_STAGE (2 * KVTILE)        // 18432
#define AT_SMEM (2 * AT_STAGE)       // 36864
#define QSTG (QT * KROWB)            // 18432

__global__ __launch_bounds__(256, 1)
void attn_mma(const __half* __restrict__ Q16, const __half* __restrict__ K16,
              const __half* __restrict__ V16, __half* __restrict__ O16) {
    extern __shared__ __align__(128) char smem[];
    const uint32_t sb = s2u(smem);
    const int tid = threadIdx.x;
    const int wid = tid >> 5;
    const int lane = tid & 31;
    const int qt = (SEQL / QT - 1) - (blockIdx.x >> 5);  // heavy tiles first
    const int bh = blockIdx.x & 31;
    const size_t hoff = (size_t)bh * SEQL * HD;

    {
        const int r = tid >> 1;
        const int cs = (tid & 1) * 4;
        const __half* qp = Q16 + hoff + (size_t)(qt * QT + r) * HD + cs * 8;
#pragma unroll
        for (int i = 0; i < 4; i++)
            cpa16(sb + r * KROWB + (cs + i) * 16, qp + i * 8);
        CP_COMMIT();
        CP_WAIT(0);
        __syncthreads();
    }
    uint32_t qa[4][4];
    {
        const uint32_t qa0 = (16 * wid + (lane & 15)) * KROWB + (lane >> 4) * 16;
#pragma unroll
        for (int kk = 0; kk < 4; kk++) ldsm4(qa[kk], sb + qa0 + kk * 32);
    }
    __syncthreads();

    auto load_kv = [&](int c, int stg) {
        const uint32_t base = sb + stg * AT_STAGE;
        const size_t g0 = hoff + (size_t)(c * ST) * HD;
#pragma unroll
        for (int i = 0; i < 2; i++) {
            const int id = tid + 256 * i;
            const int r = id >> 3;
            const int sg = id & 7;
            const uint32_t so = r * KROWB + sg * 16;
            const size_t go = g0 + (size_t)r * HD + sg * 8;
            cpa16(base + so, K16 + go);
            cpa16(base + KVTILE + so, V16 + go);
        }
        CP_COMMIT();
    };

    float m_[2] = {-1e30f, -1e30f};
    float l_[2] = {0.0f, 0.0f};
    float o[8][4];
#pragma unroll
    for (int nf = 0; nf < 8; nf++)
#pragma unroll
        for (int j = 0; j < 4; j++) o[nf][j] = 0.0f;

    const int nch = 2 * qt + 2;
    load_kv(0, 0);
    if (nch > 1) load_kv(1, 1);

    const int rowa = qt * QT + 16 * wid + (lane >> 2);
    const uint32_t xHalf = (lane >> 4) * 16;

    for (int c = 0; c < nch; c++) {
        if (c + 1 < nch) { CP_WAIT(1); } else { CP_WAIT(0); }
        __syncthreads();
        const uint32_t st = sb + (c & 1) * AT_STAGE;

        float s[8][4];
#pragma unroll
        for (int nf = 0; nf < 8; nf++)
#pragma unroll
            for (int j = 0; j < 4; j++) s[nf][j] = 0.0f;
#pragma unroll
        for (int kk = 0; kk < 4; kk++) {
#pragma unroll
            for (int nfp = 0; nfp < 4; nfp++) {
                uint32_t kq[4];
                ldsm4(kq, st + (nfp * 16 + (lane & 15)) * KROWB + kk * 32 + xHalf);
                uint32_t ke[2] = {kq[0], kq[2]};
                uint32_t ko[2] = {kq[1], kq[3]};
                mma_f16(s[2 * nfp], qa[kk], ke);
                mma_f16(s[2 * nfp + 1], qa[kk], ko);
            }
        }

        const bool diagc = (c >= 2 * qt);
#pragma unroll
        for (int nf = 0; nf < 8; nf++) {
#pragma unroll
            for (int j = 0; j < 4; j++) {
                float v = s[nf][j] * 0.125f;
                if (diagc) {
                    const int col = c * ST + nf * 8 + 2 * (lane & 3) + (j & 1);
                    const int row = rowa + ((j >> 1) << 3);
                    if (col > row) v = -1e30f;
                }
                s[nf][j] = v;
            }
        }

        float rma = -1e30f, rmb = -1e30f;
#pragma unroll
        for (int nf = 0; nf < 8; nf++) {
            rma = fmaxf(rma, fmaxf(s[nf][0], s[nf][1]));
            rmb = fmaxf(rmb, fmaxf(s[nf][2], s[nf][3]));
        }
        rma = fmaxf(rma, __shfl_xor_sync(0xffffffffu, rma, 1));
        rma = fmaxf(rma, __shfl_xor_sync(0xffffffffu, rma, 2));
        rmb = fmaxf(rmb, __shfl_xor_sync(0xffffffffu, rmb, 1));
        rmb = fmaxf(rmb, __shfl_xor_sync(0xffffffffu, rmb, 2));

        const float mna = fmaxf(m_[0], rma);
        const float mnb = fmaxf(m_[1], rmb);
        const float ca = __expf(m_[0] - mna);
        const float cb = __expf(m_[1] - mnb);
        float sa = 0.0f, sbv = 0.0f;
#pragma unroll
        for (int nf = 0; nf < 8; nf++) {
            s[nf][0] = __expf(s[nf][0] - mna);
            s[nf][1] = __expf(s[nf][1] - mna);
            s[nf][2] = __expf(s[nf][2] - mnb);
            s[nf][3] = __expf(s[nf][3] - mnb);
            sa += s[nf][0] + s[nf][1];
            sbv += s[nf][2] + s[nf][3];
        }
        sa += __shfl_xor_sync(0xffffffffu, sa, 1);
        sa += __shfl_xor_sync(0xffffffffu, sa, 2);
        sbv += __shfl_xor_sync(0xffffffffu, sbv, 1);
        sbv += __shfl_xor_sync(0xffffffffu, sbv, 2);
        l_[0] = l_[0] * ca + sa;
        l_[1] = l_[1] * cb + sbv;
        m_[0] = mna;
        m_[1] = mnb;
#pragma unroll
        for (int nf = 0; nf < 8; nf++) {
            o[nf][0] *= ca;
            o[nf][1] *= ca;
            o[nf][2] *= cb;
            o[nf][3] *= cb;
        }

#pragma unroll
        for (int kk = 0; kk < 4; kk++) {
            uint32_t ph[4];
            __half2 t0 = __floats2half2_rn(s[2 * kk][0], s[2 * kk][1]);
            __half2 t1 = __floats2half2_rn(s[2 * kk][2], s[2 * kk][3]);
            __half2 t2 = __floats2half2_rn(s[2 * kk + 1][0], s[2 * kk + 1][1]);
            __half2 t3 = __floats2half2_rn(s[2 * kk + 1][2], s[2 * kk + 1][3]);
            ph[0] = *(uint32_t*)&t0;
            ph[1] = *(uint32_t*)&t1;
            ph[2] = *(uint32_t*)&t2;
            ph[3] = *(uint32_t*)&t3;
#pragma unroll
            for (int nf = 0; nf < 8; nf++) {
                uint32_t vf[2];
                const uint32_t vo = (kk * 16 + (lane & 15)) * KROWB + nf * 16;
                ldsm2t(vf, st + KVTILE + vo);
                mma_f16(o[nf], ph, vf);
            }
        }
        __syncthreads();
        if (c + 2 < nch) load_kv(c + 2, c & 1);
    }

    const int b = bh >> 4;
    const int h = bh & 15;
    const float ia = 1.0f / l_[0];
    const float ib = 1.0f / l_[1];
#pragma unroll
    for (int nf = 0; nf < 8; nf++) {
        const int e = h * 64 + nf * 8 + 2 * (lane & 3);
        __half2 hv = __floats2half2_rn(o[nf][0] * ia, o[nf][1] * ia);
        size_t idx = (size_t)(b * SEQL + rowa) * EMB + e;
        *(uint32_t*)&O16[idx] = *(uint32_t*)&hv;
        hv = __floats2half2_rn(o[nf][2] * ib, o[nf][3] * ib);
        idx = (size_t)(b * SEQL + rowa + 8) * EMB + e;
        *(uint32_t*)&O16[idx] = *(uint32_t*)&hv;
    }
}

// ---------------- launch -----------------------------------------------------
extern "C" void kernel_launch(void* const* d_in, const int* in_sizes, int n_in,
                              void* d_out, int out_size) {
    const float* x = (const float*)d_in[0];
    const float* w_q = (const float*)d_in[1];
    const float* w_k = (const float*)d_in[2];
    const float* w_v = (const float*)d_in[3];
    const float* w_o = (const float*)d_in[4];
    float* out = (float*)d_out;

    __half *x16, *a16, *wq16, *wk16, *wv16, *wo16, *q16, *k16, *v16;
    cudaGetSymbolAddress((void**)&x16, g_x16);
    cudaGetSymbolAddress((void**)&a16, g_a16);
    cudaGetSymbolAddress((void**)&wq16, g_wq16);
    cudaGetSymbolAddress((void**)&wk16, g_wk16);
    cudaGetSymbolAddress((void**)&wv16, g_wv16);
    cudaGetSymbolAddress((void**)&wo16, g_wo16);
    cudaGetSymbolAddress((void**)&q16, g_q16);
    cudaGetSymbolAddress((void**)&k16, g_k16);
    cudaGetSymbolAddress((void**)&v16, g_v16);

    cudaFuncSetAttribute(gemm_qkv, cudaFuncAttributeMaxDynamicSharedMemorySize, SM_TOTAL);
    cudaFuncSetAttribute(gemm_out, cudaFuncAttributeMaxDynamicSharedMemorySize, SM_TOTAL);
    cudaFuncSetAttribute(attn_mma, cudaFuncAttributeMaxDynamicSharedMemorySize, AT_SMEM);

    cvt_all<<<4096 + 4 * 1024, 256>>>(x, w_q, w_k, w_v, w_o,
                                      x16, wq16, wk16, wv16, wo16);

    dim3 qkvgrid(24, 32);  // x: 3 weights x 8 n-tiles; y: 32 m-tiles
    gemm_qkv<<<qkvgrid, 256, SM_TOTAL>>>(x16, wq16, wk16, wv16, q16, k16, v16);

    attn_mma<<<(SEQL / QT) * BSZ * NH, 256, AT_SMEM>>>(q16, k16, v16, a16);

    dim3 ogrid(8, 32);
    gemm_out<<<ogrid, 256, SM_TOTAL>>>(a16, wo16, out);
}